// round 10
// baseline (speedup 1.0000x reference)
#include <cuda_runtime.h>
#include <math.h>

#define BB  512
#define SSZ 16
#define HH  501
#define CC  7

#define BM 64
#define BN 32
#define BK 32
#define NT 256
#define NKT 16          // ceil(501/32)
#define LDA_ 68         // BM+4 pad (16B-aligned stride for vector reads)
#define LDW_ 36         // BN+4 pad

// Scratch (module-scope device globals; allocation-free per harness rules)
// g_hv slot i stores hv_{i-1}: slot 0 = graph_state0, slot idx+1 = hv_idx
__device__ float g_hv[(SSZ + 1) * BB * HH];
__device__ float g_hin[BB * HH];
__device__ float g_d1[(SSZ + 1) * BB];
__device__ float g_d2[(SSZ + 1) * BB];

typedef unsigned long long u64;

__device__ __forceinline__ float sigf(float x) { return 1.0f / (1.0f + expf(-x)); }
__device__ __forceinline__ u64 pk2(float x, float y) {
    u64 r; asm("mov.b64 %0,{%1,%2};" : "=l"(r) : "f"(x), "f"(y)); return r;
}
__device__ __forceinline__ void fma2(u64& d, u64 a, u64 b) {
    asm("fma.rn.f32x2 %0,%1,%2,%0;" : "+l"(d) : "l"(a), "l"(b));
}
__device__ __forceinline__ void up2(u64 v, float& a, float& b) {
    asm("mov.b64 {%0,%1},%2;" : "=f"(a), "=f"(b) : "l"(v));
}

// Thread mapping (all GEMMs):
//   compute: tx = tid&7  -> n4 = tx*4 (4 cols);  ty = tid>>3 -> m2 = ty*2 (2 rows)
//   loads:   kz = tid&31 (k within tile), r0 = tid>>5 (0..7)
//            sA rows r0+8i (i<8), sW rows r0+8j (j<4)

// ===========================================================================
// k_gru: gh = Hsrc @ W_hh.T (3 parts fused) ; epilogue = full GRU cell.
// BM=64 x BN=32, NT=256, 2x4 microtile, double-buffered smem, FFMA2.
// ===========================================================================
__global__ __launch_bounds__(NT) void k_gru(int step, int use_hin,
        const float* __restrict__ ne,
        const float* __restrict__ Wih, const float* __restrict__ bih,
        const float* __restrict__ Whh, const float* __restrict__ bhh) {
    __shared__ __align__(16) float sA[2][BK][LDA_];
    __shared__ __align__(16) float sW[2][3][BK][LDW_];
    const int m0 = blockIdx.y * BM, n0 = blockIdx.x * BN;
    const int tid = threadIdx.x;
    const int tx = tid & 7, ty = tid >> 3;
    const int n4 = tx * 4, m2 = ty * 2;
    const int kz = tid & 31, r0 = tid >> 5;
    const float* Hsrc = use_hin ? g_hin : g_hv;

    u64 acc[3][2][2];
#pragma unroll
    for (int p = 0; p < 3; p++)
#pragma unroll
        for (int i = 0; i < 2; i++) { acc[p][i][0] = 0ull; acc[p][i][1] = 0ull; }

    float rAv[8], rWv[3][4];

    // ---- prefetch + store tile 0 ----
#pragma unroll
    for (int i = 0; i < 8; i++)
        rAv[i] = Hsrc[(m0 + r0 + 8 * i) * HH + kz];
#pragma unroll
    for (int j = 0; j < 4; j++) {
        int r = r0 + 8 * j;
        bool ok = (n0 + r) < HH;
#pragma unroll
        for (int p = 0; p < 3; p++)
            rWv[p][j] = ok ? Whh[(p * HH + n0 + r) * HH + kz] : 0.f;
    }
#pragma unroll
    for (int i = 0; i < 8; i++) sA[0][kz][r0 + 8 * i] = rAv[i];
#pragma unroll
    for (int j = 0; j < 4; j++)
#pragma unroll
        for (int p = 0; p < 3; p++) sW[0][p][kz][r0 + 8 * j] = rWv[p][j];
    __syncthreads();

    for (int t = 0; t < NKT; t++) {
        int cur = t & 1;
        if (t + 1 < NKT) {
            int gk = (t + 1) * BK + kz;
            bool okk = gk < HH;
#pragma unroll
            for (int i = 0; i < 8; i++)
                rAv[i] = okk ? Hsrc[(m0 + r0 + 8 * i) * HH + gk] : 0.f;
#pragma unroll
            for (int j = 0; j < 4; j++) {
                int r = r0 + 8 * j;
                bool ok = okk && ((n0 + r) < HH);
#pragma unroll
                for (int p = 0; p < 3; p++)
                    rWv[p][j] = ok ? Whh[(p * HH + n0 + r) * HH + gk] : 0.f;
            }
        }
#pragma unroll
        for (int kk = 0; kk < BK; kk++) {
            float2 av = *reinterpret_cast<const float2*>(&sA[cur][kk][m2]);
            u64 aa0 = pk2(av.x, av.x), aa1 = pk2(av.y, av.y);
#pragma unroll
            for (int p = 0; p < 3; p++) {
                ulonglong2 wv = *reinterpret_cast<const ulonglong2*>(&sW[cur][p][kk][n4]);
                fma2(acc[p][0][0], aa0, wv.x);
                fma2(acc[p][0][1], aa0, wv.y);
                fma2(acc[p][1][0], aa1, wv.x);
                fma2(acc[p][1][1], aa1, wv.y);
            }
        }
        if (t + 1 < NKT) {
            int nb = (t + 1) & 1;
#pragma unroll
            for (int i = 0; i < 8; i++) sA[nb][kz][r0 + 8 * i] = rAv[i];
#pragma unroll
            for (int j = 0; j < 4; j++)
#pragma unroll
                for (int p = 0; p < 3; p++) sW[nb][p][kz][r0 + 8 * j] = rWv[p][j];
            __syncthreads();
        }
    }

    // ---- epilogue: GRU cell ----
    float af[3][2][4];
#pragma unroll
    for (int p = 0; p < 3; p++)
#pragma unroll
        for (int im = 0; im < 2; im++) {
            up2(acc[p][im][0], af[p][im][0], af[p][im][1]);
            up2(acc[p][im][1], af[p][im][2], af[p][im][3]);
        }
    float* O = g_hv + (step + 1) * BB * HH;
#pragma unroll
    for (int im = 0; im < 2; im++) {
        int b = m0 + m2 + im;
        float x[CC];
#pragma unroll
        for (int c = 0; c < CC; c++) x[c] = ne[b * SSZ * CC + step * CC + c];
#pragma unroll
        for (int jn = 0; jn < 4; jn++) {
            int n = n0 + n4 + jn;
            if (n >= HH) continue;
            float gir = bih[n], giz = bih[HH + n], gin = bih[2 * HH + n];
#pragma unroll
            for (int c = 0; c < CC; c++) {
                gir += x[c] * Wih[n * CC + c];
                giz += x[c] * Wih[(HH + n) * CC + c];
                gin += x[c] * Wih[(2 * HH + n) * CC + c];
            }
            float ghr = af[0][im][jn] + bhh[n];
            float ghz = af[1][im][jn] + bhh[HH + n];
            float ghn = af[2][im][jn] + bhh[2 * HH + n];
            float r  = sigf(gir + ghr);
            float zg = sigf(giz + ghz);
            float nv = tanhf(gin + r * ghn);
            float hp = Hsrc[b * HH + n];
            O[b * HH + n] = (1.f - zg) * nv + zg * hp;
        }
    }
}

// ===========================================================================
// k_agm: masked aggregation, gate+map fused (P=2).
//   a[b,:] = hv_{step-1}[b,:] * dep[b,step,step-1]
//   g_hin  = 15*sig(bg)*bm + sig(a@Wg.T+bg) * (a@Wm.T+bm)
// ===========================================================================
__global__ __launch_bounds__(NT) void k_agm(int step,
        const float* __restrict__ dep,
        const float* __restrict__ Wg, const float* __restrict__ bg,
        const float* __restrict__ Wm, const float* __restrict__ bm) {
    __shared__ __align__(16) float sA[2][BK][LDA_];
    __shared__ __align__(16) float sW[2][2][BK][LDW_];
    const int m0 = blockIdx.y * BM, n0 = blockIdx.x * BN;
    const int tid = threadIdx.x;
    const int tx = tid & 7, ty = tid >> 3;
    const int n4 = tx * 4, m2 = ty * 2;
    const int kz = tid & 31, r0 = tid >> 5;
    const float* A = g_hv + step * BB * HH;     // hv_{step-1}

    float rMask[8];
#pragma unroll
    for (int i = 0; i < 8; i++)
        rMask[i] = dep[(m0 + r0 + 8 * i) * SSZ * SSZ + step * SSZ + (step - 1)];

    u64 acc[2][2][2];
#pragma unroll
    for (int p = 0; p < 2; p++)
#pragma unroll
        for (int i = 0; i < 2; i++) { acc[p][i][0] = 0ull; acc[p][i][1] = 0ull; }

    float rAv[8], rWv[2][4];

#pragma unroll
    for (int i = 0; i < 8; i++)
        rAv[i] = A[(m0 + r0 + 8 * i) * HH + kz] * rMask[i];
#pragma unroll
    for (int j = 0; j < 4; j++) {
        int r = r0 + 8 * j;
        bool ok = (n0 + r) < HH;
        rWv[0][j] = ok ? Wg[(n0 + r) * HH + kz] : 0.f;
        rWv[1][j] = ok ? Wm[(n0 + r) * HH + kz] : 0.f;
    }
#pragma unroll
    for (int i = 0; i < 8; i++) sA[0][kz][r0 + 8 * i] = rAv[i];
#pragma unroll
    for (int j = 0; j < 4; j++) {
        sW[0][0][kz][r0 + 8 * j] = rWv[0][j];
        sW[0][1][kz][r0 + 8 * j] = rWv[1][j];
    }
    __syncthreads();

    for (int t = 0; t < NKT; t++) {
        int cur = t & 1;
        if (t + 1 < NKT) {
            int gk = (t + 1) * BK + kz;
            bool okk = gk < HH;
#pragma unroll
            for (int i = 0; i < 8; i++)
                rAv[i] = okk ? A[(m0 + r0 + 8 * i) * HH + gk] * rMask[i] : 0.f;
#pragma unroll
            for (int j = 0; j < 4; j++) {
                int r = r0 + 8 * j;
                bool ok = okk && ((n0 + r) < HH);
                rWv[0][j] = ok ? Wg[(n0 + r) * HH + gk] : 0.f;
                rWv[1][j] = ok ? Wm[(n0 + r) * HH + gk] : 0.f;
            }
        }
#pragma unroll
        for (int kk = 0; kk < BK; kk++) {
            float2 av = *reinterpret_cast<const float2*>(&sA[cur][kk][m2]);
            u64 aa0 = pk2(av.x, av.x), aa1 = pk2(av.y, av.y);
#pragma unroll
            for (int p = 0; p < 2; p++) {
                ulonglong2 wv = *reinterpret_cast<const ulonglong2*>(&sW[cur][p][kk][n4]);
                fma2(acc[p][0][0], aa0, wv.x);
                fma2(acc[p][0][1], aa0, wv.y);
                fma2(acc[p][1][0], aa1, wv.x);
                fma2(acc[p][1][1], aa1, wv.y);
            }
        }
        if (t + 1 < NKT) {
            int nb = (t + 1) & 1;
#pragma unroll
            for (int i = 0; i < 8; i++) sA[nb][kz][r0 + 8 * i] = rAv[i];
#pragma unroll
            for (int j = 0; j < 4; j++) {
                sW[nb][0][kz][r0 + 8 * j] = rWv[0][j];
                sW[nb][1][kz][r0 + 8 * j] = rWv[1][j];
            }
            __syncthreads();
        }
    }

    float af[2][2][4];
#pragma unroll
    for (int p = 0; p < 2; p++)
#pragma unroll
        for (int im = 0; im < 2; im++) {
            up2(acc[p][im][0], af[p][im][0], af[p][im][1]);
            up2(acc[p][im][1], af[p][im][2], af[p][im][3]);
        }
#pragma unroll
    for (int jn = 0; jn < 4; jn++) {
        int n = n0 + n4 + jn;
        if (n >= HH) continue;
        float bgv = bg[n], bmv = bm[n];
        float base = 15.0f * sigf(bgv) * bmv;
#pragma unroll
        for (int im = 0; im < 2; im++) {
            int b = m0 + m2 + im;
            float u = af[0][im][jn] + bgv;
            float v = af[1][im][jn] + bmv;
            g_hin[b * HH + n] = base + sigf(u) * v;
        }
    }
}

// ===========================================================================
// k_lin1 (once): g_hv[slot0] = z @ W_lin1.T + b_lin1
// ===========================================================================
__global__ __launch_bounds__(NT) void k_lin1(const float* __restrict__ A,
                                             const float* __restrict__ W,
                                             const float* __restrict__ bias) {
    __shared__ __align__(16) float sA[2][BK][LDA_];
    __shared__ __align__(16) float sW[2][BK][LDW_];
    const int m0 = blockIdx.y * BM, n0 = blockIdx.x * BN;
    const int tid = threadIdx.x;
    const int tx = tid & 7, ty = tid >> 3;
    const int n4 = tx * 4, m2 = ty * 2;
    const int kz = tid & 31, r0 = tid >> 5;

    u64 acc[2][2];
#pragma unroll
    for (int i = 0; i < 2; i++) { acc[i][0] = 0ull; acc[i][1] = 0ull; }

    float rAv[8], rWv[4];
#pragma unroll
    for (int i = 0; i < 8; i++)
        rAv[i] = A[(m0 + r0 + 8 * i) * HH + kz];
#pragma unroll
    for (int j = 0; j < 4; j++) {
        int r = r0 + 8 * j;
        rWv[j] = ((n0 + r) < HH) ? W[(n0 + r) * HH + kz] : 0.f;
    }
#pragma unroll
    for (int i = 0; i < 8; i++) sA[0][kz][r0 + 8 * i] = rAv[i];
#pragma unroll
    for (int j = 0; j < 4; j++) sW[0][kz][r0 + 8 * j] = rWv[j];
    __syncthreads();

    for (int t = 0; t < NKT; t++) {
        int cur = t & 1;
        if (t + 1 < NKT) {
            int gk = (t + 1) * BK + kz;
            bool okk = gk < HH;
#pragma unroll
            for (int i = 0; i < 8; i++)
                rAv[i] = okk ? A[(m0 + r0 + 8 * i) * HH + gk] : 0.f;
#pragma unroll
            for (int j = 0; j < 4; j++) {
                int r = r0 + 8 * j;
                rWv[j] = (okk && ((n0 + r) < HH)) ? W[(n0 + r) * HH + gk] : 0.f;
            }
        }
#pragma unroll
        for (int kk = 0; kk < BK; kk++) {
            float2 av = *reinterpret_cast<const float2*>(&sA[cur][kk][m2]);
            u64 aa0 = pk2(av.x, av.x), aa1 = pk2(av.y, av.y);
            ulonglong2 wv = *reinterpret_cast<const ulonglong2*>(&sW[cur][kk][n4]);
            fma2(acc[0][0], aa0, wv.x);
            fma2(acc[0][1], aa0, wv.y);
            fma2(acc[1][0], aa1, wv.x);
            fma2(acc[1][1], aa1, wv.y);
        }
        if (t + 1 < NKT) {
            int nb = (t + 1) & 1;
#pragma unroll
            for (int i = 0; i < 8; i++) sA[nb][kz][r0 + 8 * i] = rAv[i];
#pragma unroll
            for (int j = 0; j < 4; j++) sW[nb][kz][r0 + 8 * j] = rWv[j];
            __syncthreads();
        }
    }

#pragma unroll
    for (int im = 0; im < 2; im++) {
        float v0, v1, v2, v3;
        up2(acc[im][0], v0, v1);
        up2(acc[im][1], v2, v3);
        int b = m0 + m2 + im;
        float vv[4] = { v0, v1, v2, v3 };
#pragma unroll
        for (int jn = 0; jn < 4; jn++) {
            int n = n0 + n4 + jn;
            if (n < HH) g_hv[b * HH + n] = vv[jn] + bias[n];
        }
    }
}

// ---------------------------------------------------------------------------
// Post: edge-logit dot products  d1[i]=w1.hv_i  d2[i]=w2.hv_i  (warp per row)
// ---------------------------------------------------------------------------
__global__ __launch_bounds__(256) void k_dots(const float* __restrict__ We) {
    int warp = threadIdx.x >> 5, lane = threadIdx.x & 31;
    int row = blockIdx.x * 8 + warp;             // < (S+1)*B, exact grid
    const float* hv = g_hv + row * HH;
    float a1 = 0.f, a2 = 0.f;
    for (int h = lane; h < HH; h += 32) {
        float v = hv[h];
        a1 += v * We[h];
        a2 += v * We[HH + h];
    }
#pragma unroll
    for (int o = 16; o; o >>= 1) {
        a1 += __shfl_xor_sync(0xffffffffu, a1, o);
        a2 += __shfl_xor_sync(0xffffffffu, a2, o);
    }
    if (lane == 0) { g_d1[row] = a1; g_d2[row] = a2; }
}

// ---------------------------------------------------------------------------
// Post: generated dep graph (hard threshold sigmoid(x)>=0.5 <=> x>=0)
// ---------------------------------------------------------------------------
__global__ void k_edges(const float* __restrict__ be_p, float* __restrict__ out) {
    int gid = blockIdx.x * blockDim.x + threadIdx.x;   // b*256 + idx*16 + j
    int j = gid & 15, idx = (gid >> 4) & 15, b = gid >> 8;
    float val = 0.f;
    if (idx > 0 && j < idx) {
        float t;
        if (j == idx - 1) t = g_d1[idx * BB + b] + g_d2[idx * BB + b];
        else              t = g_d1[(idx + 1) * BB + b] + g_d2[(j + 1) * BB + b];
        t += be_p[0];
        val = (t >= 0.f) ? 1.f : 0.f;
    }
    out[gid] = val;
}

// ---------------------------------------------------------------------------
// Post: node encodings.  enc[b,idx,:] = softmax(hv_{idx-1} @ W_vert.T + b_vert)
// ---------------------------------------------------------------------------
__global__ __launch_bounds__(256) void k_enc(const float* __restrict__ Wv,
                                             const float* __restrict__ bv,
                                             float* __restrict__ out2) {
    int warp = threadIdx.x >> 5, lane = threadIdx.x & 31;
    int row = blockIdx.x * 8 + warp;       // b*S + idx, exact grid
    int b = row >> 4, idx = row & 15;
    const float* hv = g_hv + (idx * BB + b) * HH;   // slot idx = hv_{idx-1}
    float l[CC];
#pragma unroll
    for (int c = 0; c < CC; c++) l[c] = 0.f;
    for (int h = lane; h < HH; h += 32) {
        float v = hv[h];
#pragma unroll
        for (int c = 0; c < CC; c++) l[c] += v * Wv[c * HH + h];
    }
#pragma unroll
    for (int c = 0; c < CC; c++)
#pragma unroll
        for (int o = 16; o; o >>= 1) l[c] += __shfl_xor_sync(0xffffffffu, l[c], o);
    if (lane == 0) {
        float mx = -1e30f;
#pragma unroll
        for (int c = 0; c < CC; c++) { l[c] += bv[c]; mx = fmaxf(mx, l[c]); }
        float s = 0.f;
#pragma unroll
        for (int c = 0; c < CC; c++) { l[c] = expf(l[c] - mx); s += l[c]; }
        float inv = 1.f / s;
#pragma unroll
        for (int c = 0; c < CC; c++) out2[row * CC + c] = l[c] * inv;
    }
}

// ---------------------------------------------------------------------------
extern "C" void kernel_launch(void* const* d_in, const int* in_sizes, int n_in,
                              void* d_out, int out_size) {
    const float* z      = (const float*)d_in[0];
    const float* dep    = (const float*)d_in[1];
    const float* ne     = (const float*)d_in[2];
    const float* W_lin1 = (const float*)d_in[3];
    const float* b_lin1 = (const float*)d_in[4];
    const float* W_vert = (const float*)d_in[5];
    const float* b_vert = (const float*)d_in[6];
    const float* W_edge = (const float*)d_in[7];
    const float* b_edge = (const float*)d_in[8];
    const float* W_gate = (const float*)d_in[9];
    const float* b_gate = (const float*)d_in[10];
    const float* W_map  = (const float*)d_in[11];
    const float* b_map  = (const float*)d_in[12];
    const float* W_ih   = (const float*)d_in[13];
    const float* b_ih   = (const float*)d_in[14];
    const float* W_hh   = (const float*)d_in[15];
    const float* b_hh   = (const float*)d_in[16];
    float* out = (float*)d_out;

    dim3 gg((HH + BN - 1) / BN, BB / BM);   // (16, 8) = 128 CTAs = one wave

    k_lin1<<<gg, NT>>>(z, W_lin1, b_lin1);                      // slot 0
    k_gru<<<gg, NT>>>(0, 0, ne, W_ih, b_ih, W_hh, b_hh);        // hv_0
    for (int step = 1; step < SSZ; step++) {
        k_agm<<<gg, NT>>>(step, dep, W_gate, b_gate, W_map, b_map);
        k_gru<<<gg, NT>>>(step, 1, ne, W_ih, b_ih, W_hh, b_hh);
    }
    k_dots<<<(SSZ + 1) * BB / 8, 256>>>(W_edge);
    k_edges<<<BB * SSZ * SSZ / 256, 256>>>(b_edge, out);
    k_enc<<<BB * SSZ / 8, 256>>>(W_vert, b_vert, out + BB * SSZ * SSZ);
}

// round 11
// speedup vs baseline: 1.4044x; 1.4044x over previous
#include <cuda_runtime.h>
#include <math.h>

#define BB  512
#define SSZ 16
#define HH  501
#define CC  7

#define BM 64
#define BN 32
#define BK 32
#define NT 256          // 2 K-groups x 128 threads
#define KG 256          // K-range per group (group1 covers 256..500 with masking)
#define NTG 8           // K-tiles per group
#define LDA_ 68         // BM+4 pad
#define LDW_ 36         // BN+4 pad
#define SA_SZ (BK * LDA_)          // 2176 floats per group
#define SW1_SZ (BK * LDW_)         // 1152
#define SW2_SZ (2 * BK * LDW_)     // 2304
#define SW3_SZ (3 * BK * LDW_)     // 3456

// Scratch (module-scope device globals; allocation-free per harness rules)
// g_hv slot i stores hv_{i-1}: slot 0 = graph_state0, slot idx+1 = hv_idx
__device__ float g_hv[(SSZ + 1) * BB * HH];
__device__ float g_hin[BB * HH];
__device__ float g_d1[(SSZ + 1) * BB];
__device__ float g_d2[(SSZ + 1) * BB];

typedef unsigned long long u64;

__device__ __forceinline__ float sigf(float x) { return 1.0f / (1.0f + expf(-x)); }
__device__ __forceinline__ u64 pk2(float x, float y) {
    u64 r; asm("mov.b64 %0,{%1,%2};" : "=l"(r) : "f"(x), "f"(y)); return r;
}
__device__ __forceinline__ void fma2(u64& d, u64 a, u64 b) {
    asm("fma.rn.f32x2 %0,%1,%2,%0;" : "+l"(d) : "l"(a), "l"(b));
}
__device__ __forceinline__ void add2(u64& d, u64 a) {
    asm("add.rn.f32x2 %0,%1,%0;" : "+l"(d) : "l"(a));
}
__device__ __forceinline__ void up2(u64 v, float& a, float& b) {
    asm("mov.b64 {%0,%1},%2;" : "=f"(a), "=f"(b) : "l"(v));
}
#define GBAR(g) asm volatile("bar.sync %0, 128;" :: "r"(1 + (g)) : "memory")

// Thread mapping (per 128-thread K-group, identical to R9):
//   compute: tx = l&7 -> n4 = tx*4 ; ty = l>>3 (0..15) -> m4 = ty*4
//   loads:   kz = l&31, r0 = l>>5 (0..3); sA rows r0+4i (i<16), sW rows r0+4j (j<8)

// ===========================================================================
// k_gru: gh = Hsrc @ W_hh.T (3 parts) ; split-K x2 ; epilogue = GRU cell.
// ===========================================================================
__global__ __launch_bounds__(NT) void k_gru(int step, int use_hin,
        const float* __restrict__ ne,
        const float* __restrict__ Wih, const float* __restrict__ bih,
        const float* __restrict__ Whh, const float* __restrict__ bhh) {
    __shared__ __align__(16) float smemblk[2 * (SA_SZ + SW3_SZ)];   // 45KB
    const int m0 = blockIdx.y * BM, n0 = blockIdx.x * BN;
    const int tid = threadIdx.x;
    const int g = tid >> 7, l = tid & 127;
    const int tx = l & 7, ty = l >> 3;
    const int n4 = tx * 4, m4 = ty * 4;
    const int kz = l & 31, r0 = l >> 5;
    const int kbase = g * KG;
    float* sA = smemblk + g * SA_SZ;
    float* sW = smemblk + 2 * SA_SZ + g * SW3_SZ;
    const float* Hsrc = use_hin ? g_hin : g_hv;

    u64 acc[3][4][2];
#pragma unroll
    for (int p = 0; p < 3; p++)
#pragma unroll
        for (int i = 0; i < 4; i++) { acc[p][i][0] = 0ull; acc[p][i][1] = 0ull; }

    float rAv[16], rWv[3][8];

    // prefetch tile 0
    {
        int gk = kbase + kz;
#pragma unroll
        for (int i = 0; i < 16; i++)
            rAv[i] = Hsrc[(m0 + r0 + 4 * i) * HH + gk];
#pragma unroll
        for (int j = 0; j < 8; j++) {
            int r = r0 + 4 * j;
            bool ok = (n0 + r) < HH;
#pragma unroll
            for (int p = 0; p < 3; p++)
                rWv[p][j] = ok ? Whh[(p * HH + n0 + r) * HH + gk] : 0.f;
        }
    }

    for (int t = 0; t < NTG; t++) {
        GBAR(g);
#pragma unroll
        for (int i = 0; i < 16; i++) sA[kz * LDA_ + r0 + 4 * i] = rAv[i];
#pragma unroll
        for (int j = 0; j < 8; j++)
#pragma unroll
            for (int p = 0; p < 3; p++)
                sW[(p * BK + kz) * LDW_ + r0 + 4 * j] = rWv[p][j];
        GBAR(g);
        if (t + 1 < NTG) {
            int gk = kbase + (t + 1) * BK + kz;
            bool okk = gk < HH;
#pragma unroll
            for (int i = 0; i < 16; i++)
                rAv[i] = okk ? Hsrc[(m0 + r0 + 4 * i) * HH + gk] : 0.f;
#pragma unroll
            for (int j = 0; j < 8; j++) {
                int r = r0 + 4 * j;
                bool ok = okk && ((n0 + r) < HH);
#pragma unroll
                for (int p = 0; p < 3; p++)
                    rWv[p][j] = ok ? Whh[(p * HH + n0 + r) * HH + gk] : 0.f;
            }
        }
#pragma unroll
        for (int kk = 0; kk < BK; kk++) {
            float4 av = *reinterpret_cast<const float4*>(&sA[kk * LDA_ + m4]);
            u64 aa[4] = { pk2(av.x, av.x), pk2(av.y, av.y),
                          pk2(av.z, av.z), pk2(av.w, av.w) };
#pragma unroll
            for (int p = 0; p < 3; p++) {
                ulonglong2 wv = *reinterpret_cast<const ulonglong2*>(
                                    &sW[(p * BK + kk) * LDW_ + n4]);
#pragma unroll
                for (int im = 0; im < 4; im++) {
                    fma2(acc[p][im][0], aa[im], wv.x);
                    fma2(acc[p][im][1], aa[im], wv.y);
                }
            }
        }
    }

    // ---- split-K reduction through smem ----
    u64* scratch = reinterpret_cast<u64*>(smemblk);
    __syncthreads();
    if (g == 1) {
        int c = 0;
#pragma unroll
        for (int p = 0; p < 3; p++)
#pragma unroll
            for (int im = 0; im < 4; im++)
#pragma unroll
                for (int h = 0; h < 2; h++) { scratch[c * 128 + l] = acc[p][im][h]; c++; }
    }
    __syncthreads();
    if (g == 0) {
        int c = 0;
#pragma unroll
        for (int p = 0; p < 3; p++)
#pragma unroll
            for (int im = 0; im < 4; im++)
#pragma unroll
                for (int h = 0; h < 2; h++) { add2(acc[p][im][h], scratch[c * 128 + l]); c++; }

        float af[3][4][4];
#pragma unroll
        for (int p = 0; p < 3; p++)
#pragma unroll
            for (int im = 0; im < 4; im++) {
                up2(acc[p][im][0], af[p][im][0], af[p][im][1]);
                up2(acc[p][im][1], af[p][im][2], af[p][im][3]);
            }
        float* O = g_hv + (step + 1) * BB * HH;
#pragma unroll
        for (int im = 0; im < 4; im++) {
            int b = m0 + m4 + im;
            float x[CC];
#pragma unroll
            for (int c2 = 0; c2 < CC; c2++) x[c2] = ne[b * SSZ * CC + step * CC + c2];
#pragma unroll
            for (int jn = 0; jn < 4; jn++) {
                int n = n0 + n4 + jn;
                if (n >= HH) continue;
                float gir = bih[n], giz = bih[HH + n], gin = bih[2 * HH + n];
#pragma unroll
                for (int c2 = 0; c2 < CC; c2++) {
                    gir += x[c2] * Wih[n * CC + c2];
                    giz += x[c2] * Wih[(HH + n) * CC + c2];
                    gin += x[c2] * Wih[(2 * HH + n) * CC + c2];
                }
                float ghr = af[0][im][jn] + bhh[n];
                float ghz = af[1][im][jn] + bhh[HH + n];
                float ghn = af[2][im][jn] + bhh[2 * HH + n];
                float r  = sigf(gir + ghr);
                float zg = sigf(giz + ghz);
                float nv = tanhf(gin + r * ghn);
                float hp = Hsrc[b * HH + n];
                O[b * HH + n] = (1.f - zg) * nv + zg * hp;
            }
        }
    }
}

// ===========================================================================
// k_agm: masked aggregation, gate+map fused (P=2), split-K x2.
//   a[b,:] = hv_{step-1}[b,:] * dep[b,step,step-1]
//   g_hin  = 15*sig(bg)*bm + sig(a@Wg.T+bg) * (a@Wm.T+bm)
// ===========================================================================
__global__ __launch_bounds__(NT) void k_agm(int step,
        const float* __restrict__ dep,
        const float* __restrict__ Wg, const float* __restrict__ bg,
        const float* __restrict__ Wm, const float* __restrict__ bm) {
    __shared__ __align__(16) float smemblk[2 * (SA_SZ + SW2_SZ)];   // 35.8KB
    const int m0 = blockIdx.y * BM, n0 = blockIdx.x * BN;
    const int tid = threadIdx.x;
    const int g = tid >> 7, l = tid & 127;
    const int tx = l & 7, ty = l >> 3;
    const int n4 = tx * 4, m4 = ty * 4;
    const int kz = l & 31, r0 = l >> 5;
    const int kbase = g * KG;
    float* sA = smemblk + g * SA_SZ;
    float* sW = smemblk + 2 * SA_SZ + g * SW2_SZ;
    const float* A = g_hv + step * BB * HH;     // hv_{step-1}

    float rMask[16];
#pragma unroll
    for (int i = 0; i < 16; i++)
        rMask[i] = dep[(m0 + r0 + 4 * i) * SSZ * SSZ + step * SSZ + (step - 1)];

    u64 acc[2][4][2];
#pragma unroll
    for (int p = 0; p < 2; p++)
#pragma unroll
        for (int i = 0; i < 4; i++) { acc[p][i][0] = 0ull; acc[p][i][1] = 0ull; }

    float rAv[16], rWv[2][8];
    {
        int gk = kbase + kz;
#pragma unroll
        for (int i = 0; i < 16; i++)
            rAv[i] = A[(m0 + r0 + 4 * i) * HH + gk] * rMask[i];
#pragma unroll
        for (int j = 0; j < 8; j++) {
            int r = r0 + 4 * j;
            bool ok = (n0 + r) < HH;
            rWv[0][j] = ok ? Wg[(n0 + r) * HH + gk] : 0.f;
            rWv[1][j] = ok ? Wm[(n0 + r) * HH + gk] : 0.f;
        }
    }

    for (int t = 0; t < NTG; t++) {
        GBAR(g);
#pragma unroll
        for (int i = 0; i < 16; i++) sA[kz * LDA_ + r0 + 4 * i] = rAv[i];
#pragma unroll
        for (int j = 0; j < 8; j++) {
            sW[kz * LDW_ + r0 + 4 * j] = rWv[0][j];
            sW[(BK + kz) * LDW_ + r0 + 4 * j] = rWv[1][j];
        }
        GBAR(g);
        if (t + 1 < NTG) {
            int gk = kbase + (t + 1) * BK + kz;
            bool okk = gk < HH;
#pragma unroll
            for (int i = 0; i < 16; i++)
                rAv[i] = okk ? A[(m0 + r0 + 4 * i) * HH + gk] * rMask[i] : 0.f;
#pragma unroll
            for (int j = 0; j < 8; j++) {
                int r = r0 + 4 * j;
                bool ok = okk && ((n0 + r) < HH);
                rWv[0][j] = ok ? Wg[(n0 + r) * HH + gk] : 0.f;
                rWv[1][j] = ok ? Wm[(n0 + r) * HH + gk] : 0.f;
            }
        }
#pragma unroll
        for (int kk = 0; kk < BK; kk++) {
            float4 av = *reinterpret_cast<const float4*>(&sA[kk * LDA_ + m4]);
            u64 aa[4] = { pk2(av.x, av.x), pk2(av.y, av.y),
                          pk2(av.z, av.z), pk2(av.w, av.w) };
#pragma unroll
            for (int p = 0; p < 2; p++) {
                ulonglong2 wv = *reinterpret_cast<const ulonglong2*>(
                                    &sW[(p * BK + kk) * LDW_ + n4]);
#pragma unroll
                for (int im = 0; im < 4; im++) {
                    fma2(acc[p][im][0], aa[im], wv.x);
                    fma2(acc[p][im][1], aa[im], wv.y);
                }
            }
        }
    }

    u64* scratch = reinterpret_cast<u64*>(smemblk);
    __syncthreads();
    if (g == 1) {
        int c = 0;
#pragma unroll
        for (int p = 0; p < 2; p++)
#pragma unroll
            for (int im = 0; im < 4; im++)
#pragma unroll
                for (int h = 0; h < 2; h++) { scratch[c * 128 + l] = acc[p][im][h]; c++; }
    }
    __syncthreads();
    if (g == 0) {
        int c = 0;
#pragma unroll
        for (int p = 0; p < 2; p++)
#pragma unroll
            for (int im = 0; im < 4; im++)
#pragma unroll
                for (int h = 0; h < 2; h++) { add2(acc[p][im][h], scratch[c * 128 + l]); c++; }

        float af[2][4][4];
#pragma unroll
        for (int p = 0; p < 2; p++)
#pragma unroll
            for (int im = 0; im < 4; im++) {
                up2(acc[p][im][0], af[p][im][0], af[p][im][1]);
                up2(acc[p][im][1], af[p][im][2], af[p][im][3]);
            }
#pragma unroll
        for (int jn = 0; jn < 4; jn++) {
            int n = n0 + n4 + jn;
            if (n >= HH) continue;
            float bgv = bg[n], bmv = bm[n];
            float base = 15.0f * sigf(bgv) * bmv;
#pragma unroll
            for (int im = 0; im < 4; im++) {
                int b = m0 + m4 + im;
                float u = af[0][im][jn] + bgv;
                float v = af[1][im][jn] + bmv;
                g_hin[b * HH + n] = base + sigf(u) * v;
            }
        }
    }
}

// ===========================================================================
// k_lin1 (once): g_hv[slot0] = z @ W_lin1.T + b_lin1, split-K x2.
// ===========================================================================
__global__ __launch_bounds__(NT) void k_lin1(const float* __restrict__ A,
                                             const float* __restrict__ W,
                                             const float* __restrict__ bias) {
    __shared__ __align__(16) float smemblk[2 * (SA_SZ + SW1_SZ)];   // 26.6KB
    const int m0 = blockIdx.y * BM, n0 = blockIdx.x * BN;
    const int tid = threadIdx.x;
    const int g = tid >> 7, l = tid & 127;
    const int tx = l & 7, ty = l >> 3;
    const int n4 = tx * 4, m4 = ty * 4;
    const int kz = l & 31, r0 = l >> 5;
    const int kbase = g * KG;
    float* sA = smemblk + g * SA_SZ;
    float* sW = smemblk + 2 * SA_SZ + g * SW1_SZ;

    u64 acc[4][2];
#pragma unroll
    for (int i = 0; i < 4; i++) { acc[i][0] = 0ull; acc[i][1] = 0ull; }

    float rAv[16], rWv[8];
    {
        int gk = kbase + kz;
#pragma unroll
        for (int i = 0; i < 16; i++)
            rAv[i] = A[(m0 + r0 + 4 * i) * HH + gk];
#pragma unroll
        for (int j = 0; j < 8; j++) {
            int r = r0 + 4 * j;
            rWv[j] = ((n0 + r) < HH) ? W[(n0 + r) * HH + gk] : 0.f;
        }
    }

    for (int t = 0; t < NTG; t++) {
        GBAR(g);
#pragma unroll
        for (int i = 0; i < 16; i++) sA[kz * LDA_ + r0 + 4 * i] = rAv[i];
#pragma unroll
        for (int j = 0; j < 8; j++) sW[kz * LDW_ + r0 + 4 * j] = rWv[j];
        GBAR(g);
        if (t + 1 < NTG) {
            int gk = kbase + (t + 1) * BK + kz;
            bool okk = gk < HH;
#pragma unroll
            for (int i = 0; i < 16; i++)
                rAv[i] = okk ? A[(m0 + r0 + 4 * i) * HH + gk] : 0.f;
#pragma unroll
            for (int j = 0; j < 8; j++) {
                int r = r0 + 4 * j;
                rWv[j] = (okk && ((n0 + r) < HH)) ? W[(n0 + r) * HH + gk] : 0.f;
            }
        }
#pragma unroll
        for (int kk = 0; kk < BK; kk++) {
            float4 av = *reinterpret_cast<const float4*>(&sA[kk * LDA_ + m4]);
            u64 aa[4] = { pk2(av.x, av.x), pk2(av.y, av.y),
                          pk2(av.z, av.z), pk2(av.w, av.w) };
            ulonglong2 wv = *reinterpret_cast<const ulonglong2*>(&sW[kk * LDW_ + n4]);
#pragma unroll
            for (int im = 0; im < 4; im++) {
                fma2(acc[im][0], aa[im], wv.x);
                fma2(acc[im][1], aa[im], wv.y);
            }
        }
    }

    u64* scratch = reinterpret_cast<u64*>(smemblk);
    __syncthreads();
    if (g == 1) {
        int c = 0;
#pragma unroll
        for (int im = 0; im < 4; im++)
#pragma unroll
            for (int h = 0; h < 2; h++) { scratch[c * 128 + l] = acc[im][h]; c++; }
    }
    __syncthreads();
    if (g == 0) {
        int c = 0;
#pragma unroll
        for (int im = 0; im < 4; im++)
#pragma unroll
            for (int h = 0; h < 2; h++) { add2(acc[im][h], scratch[c * 128 + l]); c++; }
#pragma unroll
        for (int im = 0; im < 4; im++) {
            float v0, v1, v2, v3;
            up2(acc[im][0], v0, v1);
            up2(acc[im][1], v2, v3);
            int b = m0 + m4 + im;
            float vv[4] = { v0, v1, v2, v3 };
#pragma unroll
            for (int jn = 0; jn < 4; jn++) {
                int n = n0 + n4 + jn;
                if (n < HH) g_hv[b * HH + n] = vv[jn] + bias[n];
            }
        }
    }
}

// ---------------------------------------------------------------------------
// Post: edge-logit dot products  d1[i]=w1.hv_i  d2[i]=w2.hv_i  (warp per row)
// ---------------------------------------------------------------------------
__global__ __launch_bounds__(256) void k_dots(const float* __restrict__ We) {
    int warp = threadIdx.x >> 5, lane = threadIdx.x & 31;
    int row = blockIdx.x * 8 + warp;             // < (S+1)*B, exact grid
    const float* hv = g_hv + row * HH;
    float a1 = 0.f, a2 = 0.f;
    for (int h = lane; h < HH; h += 32) {
        float v = hv[h];
        a1 += v * We[h];
        a2 += v * We[HH + h];
    }
#pragma unroll
    for (int o = 16; o; o >>= 1) {
        a1 += __shfl_xor_sync(0xffffffffu, a1, o);
        a2 += __shfl_xor_sync(0xffffffffu, a2, o);
    }
    if (lane == 0) { g_d1[row] = a1; g_d2[row] = a2; }
}

// ---------------------------------------------------------------------------
// Post: generated dep graph (hard threshold sigmoid(x)>=0.5 <=> x>=0)
// ---------------------------------------------------------------------------
__global__ void k_edges(const float* __restrict__ be_p, float* __restrict__ out) {
    int gid = blockIdx.x * blockDim.x + threadIdx.x;   // b*256 + idx*16 + j
    int j = gid & 15, idx = (gid >> 4) & 15, b = gid >> 8;
    float val = 0.f;
    if (idx > 0 && j < idx) {
        float t;
        if (j == idx - 1) t = g_d1[idx * BB + b] + g_d2[idx * BB + b];
        else              t = g_d1[(idx + 1) * BB + b] + g_d2[(j + 1) * BB + b];
        t += be_p[0];
        val = (t >= 0.f) ? 1.f : 0.f;
    }
    out[gid] = val;
}

// ---------------------------------------------------------------------------
// Post: node encodings.  enc[b,idx,:] = softmax(hv_{idx-1} @ W_vert.T + b_vert)
// ---------------------------------------------------------------------------
__global__ __launch_bounds__(256) void k_enc(const float* __restrict__ Wv,
                                             const float* __restrict__ bv,
                                             float* __restrict__ out2) {
    int warp = threadIdx.x >> 5, lane = threadIdx.x & 31;
    int row = blockIdx.x * 8 + warp;       // b*S + idx, exact grid
    int b = row >> 4, idx = row & 15;
    const float* hv = g_hv + (idx * BB + b) * HH;   // slot idx = hv_{idx-1}
    float l[CC];
#pragma unroll
    for (int c = 0; c < CC; c++) l[c] = 0.f;
    for (int h = lane; h < HH; h += 32) {
        float v = hv[h];
#pragma unroll
        for (int c = 0; c < CC; c++) l[c] += v * Wv[c * HH + h];
    }
#pragma unroll
    for (int c = 0; c < CC; c++)
#pragma unroll
        for (int o = 16; o; o >>= 1) l[c] += __shfl_xor_sync(0xffffffffu, l[c], o);
    if (lane == 0) {
        float mx = -1e30f;
#pragma unroll
        for (int c = 0; c < CC; c++) { l[c] += bv[c]; mx = fmaxf(mx, l[c]); }
        float s = 0.f;
#pragma unroll
        for (int c = 0; c < CC; c++) { l[c] = expf(l[c] - mx); s += l[c]; }
        float inv = 1.f / s;
#pragma unroll
        for (int c = 0; c < CC; c++) out2[row * CC + c] = l[c] * inv;
    }
}

// ---------------------------------------------------------------------------
extern "C" void kernel_launch(void* const* d_in, const int* in_sizes, int n_in,
                              void* d_out, int out_size) {
    const float* z      = (const float*)d_in[0];
    const float* dep    = (const float*)d_in[1];
    const float* ne     = (const float*)d_in[2];
    const float* W_lin1 = (const float*)d_in[3];
    const float* b_lin1 = (const float*)d_in[4];
    const float* W_vert = (const float*)d_in[5];
    const float* b_vert = (const float*)d_in[6];
    const float* W_edge = (const float*)d_in[7];
    const float* b_edge = (const float*)d_in[8];
    const float* W_gate = (const float*)d_in[9];
    const float* b_gate = (const float*)d_in[10];
    const float* W_map  = (const float*)d_in[11];
    const float* b_map  = (const float*)d_in[12];
    const float* W_ih   = (const float*)d_in[13];
    const float* b_ih   = (const float*)d_in[14];
    const float* W_hh   = (const float*)d_in[15];
    const float* b_hh   = (const float*)d_in[16];
    float* out = (float*)d_out;

    dim3 gg((HH + BN - 1) / BN, BB / BM);   // (16, 8) = 128 CTAs = one wave

    k_lin1<<<gg, NT>>>(z, W_lin1, b_lin1);                      // slot 0
    k_gru<<<gg, NT>>>(0, 0, ne, W_ih, b_ih, W_hh, b_hh);        // hv_0
    for (int step = 1; step < SSZ; step++) {
        k_agm<<<gg, NT>>>(step, dep, W_gate, b_gate, W_map, b_map);
        k_gru<<<gg, NT>>>(step, 1, ne, W_ih, b_ih, W_hh, b_hh);
    }
    k_dots<<<(SSZ + 1) * BB / 8, 256>>>(W_edge);
    k_edges<<<BB * SSZ * SSZ / 256, 256>>>(b_edge, out);
    k_enc<<<BB * SSZ / 8, 256>>>(W_vert, b_vert, out + BB * SSZ * SSZ);
}

// round 13
// speedup vs baseline: 1.4740x; 1.0495x over previous
#include <cuda_runtime.h>
#include <math.h>

#define BB  512
#define SSZ 16
#define HH  501
#define CC  7

#define BM 64
#define BN 32
#define BK 32
#define NT 512          // 4 K-groups x 128 threads
#define KG 128          // K-range per group
#define NTG 4           // K-tiles per group
#define NGRP 4
#define LDA_ 68         // BM+4 pad
#define LDW_ 36         // BN+4 pad
#define SA_SZ (BK * LDA_)          // 2176 floats per group
#define SW1_SZ (BK * LDW_)         // 1152
#define SW2_SZ (2 * BK * LDW_)     // 2304
#define SW3_SZ (3 * BK * LDW_)     // 3456

#define GRU_SMEM (NGRP * (SA_SZ + SW3_SZ) * 4)   // 90112 B
#define AGM_SMEM (NGRP * (SA_SZ + SW2_SZ) * 4)   // 71680 B
#define LIN_SMEM (NGRP * (SA_SZ + SW1_SZ) * 4)   // 53248 B

// Scratch (module-scope device globals; allocation-free per harness rules)
// g_hv slot i stores hv_{i-1}: slot 0 = graph_state0, slot idx+1 = hv_idx
__device__ float g_hv[(SSZ + 1) * BB * HH];
__device__ float g_hin[BB * HH];
__device__ float g_d1[(SSZ + 1) * BB];
__device__ float g_d2[(SSZ + 1) * BB];

typedef unsigned long long u64;

__device__ __forceinline__ float sigf(float x) { return 1.0f / (1.0f + expf(-x)); }
__device__ __forceinline__ u64 pk2(float x, float y) {
    u64 r; asm("mov.b64 %0,{%1,%2};" : "=l"(r) : "f"(x), "f"(y)); return r;
}
__device__ __forceinline__ void fma2(u64& d, u64 a, u64 b) {
    asm("fma.rn.f32x2 %0,%1,%2,%0;" : "+l"(d) : "l"(a), "l"(b));
}
__device__ __forceinline__ void add2(u64& d, u64 a) {
    asm("add.rn.f32x2 %0,%1,%0;" : "+l"(d) : "l"(a));
}
__device__ __forceinline__ void up2(u64 v, float& a, float& b) {
    asm("mov.b64 {%0,%1},%2;" : "=f"(a), "=f"(b) : "l"(v));
}
#define GBAR(g) asm volatile("bar.sync %0, 128;" :: "r"(1 + (g)) : "memory")

// Per 128-thread K-group thread mapping:
//   compute: tx = l&7 -> n4 = tx*4 ; ty = l>>3 (0..15) -> m4 = ty*4
//   loads:   kz = l&31, r0 = l>>5 (0..3); sA rows r0+4i (i<16), sW rows r0+4j (j<8)

// ===========================================================================
// k_gru: gh = Hsrc @ W_hh.T (3 parts) ; split-K x4 ; epilogue = GRU cell.
// ===========================================================================
__global__ __launch_bounds__(NT) void k_gru(int step, int use_hin,
        const float* __restrict__ ne,
        const float* __restrict__ Wih, const float* __restrict__ bih,
        const float* __restrict__ Whh, const float* __restrict__ bhh) {
    extern __shared__ __align__(16) float smemblk[];
    const int m0 = blockIdx.y * BM, n0 = blockIdx.x * BN;
    const int tid = threadIdx.x;
    const int g = tid >> 7, l = tid & 127;
    const int tx = l & 7, ty = l >> 3;
    const int n4 = tx * 4, m4 = ty * 4;
    const int kz = l & 31, r0 = l >> 5;
    const int kbase = g * KG;
    float* sA = smemblk + g * SA_SZ;
    float* sW = smemblk + NGRP * SA_SZ + g * SW3_SZ;
    const float* Hsrc = use_hin ? g_hin : g_hv;

    u64 acc[3][4][2];
#pragma unroll
    for (int p = 0; p < 3; p++)
#pragma unroll
        for (int i = 0; i < 4; i++) { acc[p][i][0] = 0ull; acc[p][i][1] = 0ull; }

    float rAv[16], rWv[3][8];

    // prefetch tile 0 (gk <= 384+31 < 501, no k-mask needed)
    {
        int gk = kbase + kz;
#pragma unroll
        for (int i = 0; i < 16; i++)
            rAv[i] = Hsrc[(m0 + r0 + 4 * i) * HH + gk];
#pragma unroll
        for (int j = 0; j < 8; j++) {
            int r = r0 + 4 * j;
            bool ok = (n0 + r) < HH;
#pragma unroll
            for (int p = 0; p < 3; p++)
                rWv[p][j] = ok ? Whh[(p * HH + n0 + r) * HH + gk] : 0.f;
        }
    }

    for (int t = 0; t < NTG; t++) {
        GBAR(g);
#pragma unroll
        for (int i = 0; i < 16; i++) sA[kz * LDA_ + r0 + 4 * i] = rAv[i];
#pragma unroll
        for (int j = 0; j < 8; j++)
#pragma unroll
            for (int p = 0; p < 3; p++)
                sW[(p * BK + kz) * LDW_ + r0 + 4 * j] = rWv[p][j];
        GBAR(g);
        if (t + 1 < NTG) {
            int gk = kbase + (t + 1) * BK + kz;
            bool okk = gk < HH;
#pragma unroll
            for (int i = 0; i < 16; i++)
                rAv[i] = okk ? Hsrc[(m0 + r0 + 4 * i) * HH + gk] : 0.f;
#pragma unroll
            for (int j = 0; j < 8; j++) {
                int r = r0 + 4 * j;
                bool ok = okk && ((n0 + r) < HH);
#pragma unroll
                for (int p = 0; p < 3; p++)
                    rWv[p][j] = ok ? Whh[(p * HH + n0 + r) * HH + gk] : 0.f;
            }
        }
#pragma unroll
        for (int kk = 0; kk < BK; kk++) {
            float4 av = *reinterpret_cast<const float4*>(&sA[kk * LDA_ + m4]);
            u64 aa[4] = { pk2(av.x, av.x), pk2(av.y, av.y),
                          pk2(av.z, av.z), pk2(av.w, av.w) };
#pragma unroll
            for (int p = 0; p < 3; p++) {
                ulonglong2 wv = *reinterpret_cast<const ulonglong2*>(
                                    &sW[(p * BK + kk) * LDW_ + n4]);
#pragma unroll
                for (int im = 0; im < 4; im++) {
                    fma2(acc[p][im][0], aa[im], wv.x);
                    fma2(acc[p][im][1], aa[im], wv.y);
                }
            }
        }
    }

    // ---- split-K reduction through smem (groups 1..3 -> group 0) ----
    u64* scratch = reinterpret_cast<u64*>(smemblk);
    __syncthreads();
    if (g > 0) {
        int c = 0;
#pragma unroll
        for (int p = 0; p < 3; p++)
#pragma unroll
            for (int im = 0; im < 4; im++)
#pragma unroll
                for (int h = 0; h < 2; h++) {
                    scratch[((g - 1) * 24 + c) * 128 + l] = acc[p][im][h]; c++;
                }
    }
    __syncthreads();
    if (g == 0) {
#pragma unroll
        for (int gi = 0; gi < 3; gi++) {
            int c = 0;
#pragma unroll
            for (int p = 0; p < 3; p++)
#pragma unroll
                for (int im = 0; im < 4; im++)
#pragma unroll
                    for (int h = 0; h < 2; h++) {
                        add2(acc[p][im][h], scratch[(gi * 24 + c) * 128 + l]); c++;
                    }
        }

        float af[3][4][4];
#pragma unroll
        for (int p = 0; p < 3; p++)
#pragma unroll
            for (int im = 0; im < 4; im++) {
                up2(acc[p][im][0], af[p][im][0], af[p][im][1]);
                up2(acc[p][im][1], af[p][im][2], af[p][im][3]);
            }
        float* O = g_hv + (step + 1) * BB * HH;
#pragma unroll
        for (int im = 0; im < 4; im++) {
            int b = m0 + m4 + im;
            float x[CC];
#pragma unroll
            for (int c2 = 0; c2 < CC; c2++) x[c2] = ne[b * SSZ * CC + step * CC + c2];
#pragma unroll
            for (int jn = 0; jn < 4; jn++) {
                int n = n0 + n4 + jn;
                if (n >= HH) continue;
                float gir = bih[n], giz = bih[HH + n], gin = bih[2 * HH + n];
#pragma unroll
                for (int c2 = 0; c2 < CC; c2++) {
                    gir += x[c2] * Wih[n * CC + c2];
                    giz += x[c2] * Wih[(HH + n) * CC + c2];
                    gin += x[c2] * Wih[(2 * HH + n) * CC + c2];
                }
                float ghr = af[0][im][jn] + bhh[n];
                float ghz = af[1][im][jn] + bhh[HH + n];
                float ghn = af[2][im][jn] + bhh[2 * HH + n];
                float r  = sigf(gir + ghr);
                float zg = sigf(giz + ghz);
                float nv = tanhf(gin + r * ghn);
                float hp = Hsrc[b * HH + n];
                O[b * HH + n] = (1.f - zg) * nv + zg * hp;
            }
        }
    }
}

// ===========================================================================
// k_agm: masked aggregation, gate+map fused (P=2), split-K x4.
//   a[b,:] = hv_{step-1}[b,:] * dep[b,step,step-1]
//   g_hin  = 15*sig(bg)*bm + sig(a@Wg.T+bg) * (a@Wm.T+bm)
// ===========================================================================
__global__ __launch_bounds__(NT) void k_agm(int step,
        const float* __restrict__ dep,
        const float* __restrict__ Wg, const float* __restrict__ bg,
        const float* __restrict__ Wm, const float* __restrict__ bm) {
    extern __shared__ __align__(16) float smemblk[];
    const int m0 = blockIdx.y * BM, n0 = blockIdx.x * BN;
    const int tid = threadIdx.x;
    const int g = tid >> 7, l = tid & 127;
    const int tx = l & 7, ty = l >> 3;
    const int n4 = tx * 4, m4 = ty * 4;
    const int kz = l & 31, r0 = l >> 5;
    const int kbase = g * KG;
    float* sA = smemblk + g * SA_SZ;
    float* sW = smemblk + NGRP * SA_SZ + g * SW2_SZ;
    const float* A = g_hv + step * BB * HH;     // hv_{step-1}

    float rMask[16];
#pragma unroll
    for (int i = 0; i < 16; i++)
        rMask[i] = dep[(m0 + r0 + 4 * i) * SSZ * SSZ + step * SSZ + (step - 1)];

    u64 acc[2][4][2];
#pragma unroll
    for (int p = 0; p < 2; p++)
#pragma unroll
        for (int i = 0; i < 4; i++) { acc[p][i][0] = 0ull; acc[p][i][1] = 0ull; }

    float rAv[16], rWv[2][8];
    {
        int gk = kbase + kz;
#pragma unroll
        for (int i = 0; i < 16; i++)
            rAv[i] = A[(m0 + r0 + 4 * i) * HH + gk] * rMask[i];
#pragma unroll
        for (int j = 0; j < 8; j++) {
            int r = r0 + 4 * j;
            bool ok = (n0 + r) < HH;
            rWv[0][j] = ok ? Wg[(n0 + r) * HH + gk] : 0.f;
            rWv[1][j] = ok ? Wm[(n0 + r) * HH + gk] : 0.f;
        }
    }

    for (int t = 0; t < NTG; t++) {
        GBAR(g);
#pragma unroll
        for (int i = 0; i < 16; i++) sA[kz * LDA_ + r0 + 4 * i] = rAv[i];
#pragma unroll
        for (int j = 0; j < 8; j++) {
            sW[kz * LDW_ + r0 + 4 * j] = rWv[0][j];
            sW[(BK + kz) * LDW_ + r0 + 4 * j] = rWv[1][j];
        }
        GBAR(g);
        if (t + 1 < NTG) {
            int gk = kbase + (t + 1) * BK + kz;
            bool okk = gk < HH;
#pragma unroll
            for (int i = 0; i < 16; i++)
                rAv[i] = okk ? A[(m0 + r0 + 4 * i) * HH + gk] * rMask[i] : 0.f;
#pragma unroll
            for (int j = 0; j < 8; j++) {
                int r = r0 + 4 * j;
                bool ok = okk && ((n0 + r) < HH);
                rWv[0][j] = ok ? Wg[(n0 + r) * HH + gk] : 0.f;
                rWv[1][j] = ok ? Wm[(n0 + r) * HH + gk] : 0.f;
            }
        }
#pragma unroll
        for (int kk = 0; kk < BK; kk++) {
            float4 av = *reinterpret_cast<const float4*>(&sA[kk * LDA_ + m4]);
            u64 aa[4] = { pk2(av.x, av.x), pk2(av.y, av.y),
                          pk2(av.z, av.z), pk2(av.w, av.w) };
#pragma unroll
            for (int p = 0; p < 2; p++) {
                ulonglong2 wv = *reinterpret_cast<const ulonglong2*>(
                                    &sW[(p * BK + kk) * LDW_ + n4]);
#pragma unroll
                for (int im = 0; im < 4; im++) {
                    fma2(acc[p][im][0], aa[im], wv.x);
                    fma2(acc[p][im][1], aa[im], wv.y);
                }
            }
        }
    }

    u64* scratch = reinterpret_cast<u64*>(smemblk);
    __syncthreads();
    if (g > 0) {
        int c = 0;
#pragma unroll
        for (int p = 0; p < 2; p++)
#pragma unroll
            for (int im = 0; im < 4; im++)
#pragma unroll
                for (int h = 0; h < 2; h++) {
                    scratch[((g - 1) * 16 + c) * 128 + l] = acc[p][im][h]; c++;
                }
    }
    __syncthreads();
    if (g == 0) {
#pragma unroll
        for (int gi = 0; gi < 3; gi++) {
            int c = 0;
#pragma unroll
            for (int p = 0; p < 2; p++)
#pragma unroll
                for (int im = 0; im < 4; im++)
#pragma unroll
                    for (int h = 0; h < 2; h++) {
                        add2(acc[p][im][h], scratch[(gi * 16 + c) * 128 + l]); c++;
                    }
        }

        float af[2][4][4];
#pragma unroll
        for (int p = 0; p < 2; p++)
#pragma unroll
            for (int im = 0; im < 4; im++) {
                up2(acc[p][im][0], af[p][im][0], af[p][im][1]);
                up2(acc[p][im][1], af[p][im][2], af[p][im][3]);
            }
#pragma unroll
        for (int jn = 0; jn < 4; jn++) {
            int n = n0 + n4 + jn;
            if (n >= HH) continue;
            float bgv = bg[n], bmv = bm[n];
            float base = 15.0f * sigf(bgv) * bmv;
#pragma unroll
            for (int im = 0; im < 4; im++) {
                int b = m0 + m4 + im;
                float u = af[0][im][jn] + bgv;
                float v = af[1][im][jn] + bmv;
                g_hin[b * HH + n] = base + sigf(u) * v;
            }
        }
    }
}

// ===========================================================================
// k_lin1 (once): g_hv[slot0] = z @ W_lin1.T + b_lin1, split-K x4.
// ===========================================================================
__global__ __launch_bounds__(NT) void k_lin1(const float* __restrict__ A,
                                             const float* __restrict__ W,
                                             const float* __restrict__ bias) {
    extern __shared__ __align__(16) float smemblk[];
    const int m0 = blockIdx.y * BM, n0 = blockIdx.x * BN;
    const int tid = threadIdx.x;
    const int g = tid >> 7, l = tid & 127;
    const int tx = l & 7, ty = l >> 3;
    const int n4 = tx * 4, m4 = ty * 4;
    const int kz = l & 31, r0 = l >> 5;
    const int kbase = g * KG;
    float* sA = smemblk + g * SA_SZ;
    float* sW = smemblk + NGRP * SA_SZ + g * SW1_SZ;

    u64 acc[4][2];
#pragma unroll
    for (int i = 0; i < 4; i++) { acc[i][0] = 0ull; acc[i][1] = 0ull; }

    float rAv[16], rWv[8];
    {
        int gk = kbase + kz;
#pragma unroll
        for (int i = 0; i < 16; i++)
            rAv[i] = A[(m0 + r0 + 4 * i) * HH + gk];
#pragma unroll
        for (int j = 0; j < 8; j++) {
            int r = r0 + 4 * j;
            rWv[j] = ((n0 + r) < HH) ? W[(n0 + r) * HH + gk] : 0.f;
        }
    }

    for (int t = 0; t < NTG; t++) {
        GBAR(g);
#pragma unroll
        for (int i = 0; i < 16; i++) sA[kz * LDA_ + r0 + 4 * i] = rAv[i];
#pragma unroll
        for (int j = 0; j < 8; j++) sW[kz * LDW_ + r0 + 4 * j] = rWv[j];
        GBAR(g);
        if (t + 1 < NTG) {
            int gk = kbase + (t + 1) * BK + kz;
            bool okk = gk < HH;
#pragma unroll
            for (int i = 0; i < 16; i++)
                rAv[i] = okk ? A[(m0 + r0 + 4 * i) * HH + gk] : 0.f;
#pragma unroll
            for (int j = 0; j < 8; j++) {
                int r = r0 + 4 * j;
                rWv[j] = (okk && ((n0 + r) < HH)) ? W[(n0 + r) * HH + gk] : 0.f;
            }
        }
#pragma unroll
        for (int kk = 0; kk < BK; kk++) {
            float4 av = *reinterpret_cast<const float4*>(&sA[kk * LDA_ + m4]);
            u64 aa[4] = { pk2(av.x, av.x), pk2(av.y, av.y),
                          pk2(av.z, av.z), pk2(av.w, av.w) };
            ulonglong2 wv = *reinterpret_cast<const ulonglong2*>(&sW[kk * LDW_ + n4]);
#pragma unroll
            for (int im = 0; im < 4; im++) {
                fma2(acc[im][0], aa[im], wv.x);
                fma2(acc[im][1], aa[im], wv.y);
            }
        }
    }

    u64* scratch = reinterpret_cast<u64*>(smemblk);
    __syncthreads();
    if (g > 0) {
        int c = 0;
#pragma unroll
        for (int im = 0; im < 4; im++)
#pragma unroll
            for (int h = 0; h < 2; h++) {
                scratch[((g - 1) * 8 + c) * 128 + l] = acc[im][h]; c++;
            }
    }
    __syncthreads();
    if (g == 0) {
#pragma unroll
        for (int gi = 0; gi < 3; gi++) {
            int c = 0;
#pragma unroll
            for (int im = 0; im < 4; im++)
#pragma unroll
                for (int h = 0; h < 2; h++) {
                    add2(acc[im][h], scratch[(gi * 8 + c) * 128 + l]); c++;
                }
        }
#pragma unroll
        for (int im = 0; im < 4; im++) {
            float v0, v1, v2, v3;
            up2(acc[im][0], v0, v1);
            up2(acc[im][1], v2, v3);
            int b = m0 + m4 + im;
            float vv[4] = { v0, v1, v2, v3 };
#pragma unroll
            for (int jn = 0; jn < 4; jn++) {
                int n = n0 + n4 + jn;
                if (n < HH) g_hv[b * HH + n] = vv[jn] + bias[n];
            }
        }
    }
}

// ---------------------------------------------------------------------------
// Post: edge-logit dot products  d1[i]=w1.hv_i  d2[i]=w2.hv_i  (warp per row)
// ---------------------------------------------------------------------------
__global__ __launch_bounds__(256) void k_dots(const float* __restrict__ We) {
    int warp = threadIdx.x >> 5, lane = threadIdx.x & 31;
    int row = blockIdx.x * 8 + warp;             // < (S+1)*B, exact grid
    const float* hv = g_hv + row * HH;
    float a1 = 0.f, a2 = 0.f;
    for (int h = lane; h < HH; h += 32) {
        float v = hv[h];
        a1 += v * We[h];
        a2 += v * We[HH + h];
    }
#pragma unroll
    for (int o = 16; o; o >>= 1) {
        a1 += __shfl_xor_sync(0xffffffffu, a1, o);
        a2 += __shfl_xor_sync(0xffffffffu, a2, o);
    }
    if (lane == 0) { g_d1[row] = a1; g_d2[row] = a2; }
}

// ---------------------------------------------------------------------------
// Post: generated dep graph (hard threshold sigmoid(x)>=0.5 <=> x>=0)
// ---------------------------------------------------------------------------
__global__ void k_edges(const float* __restrict__ be_p, float* __restrict__ out) {
    int gid = blockIdx.x * blockDim.x + threadIdx.x;   // b*256 + idx*16 + j
    int j = gid & 15, idx = (gid >> 4) & 15, b = gid >> 8;
    float val = 0.f;
    if (idx > 0 && j < idx) {
        float t;
        if (j == idx - 1) t = g_d1[idx * BB + b] + g_d2[idx * BB + b];
        else              t = g_d1[(idx + 1) * BB + b] + g_d2[(j + 1) * BB + b];
        t += be_p[0];
        val = (t >= 0.f) ? 1.f : 0.f;
    }
    out[gid] = val;
}

// ---------------------------------------------------------------------------
// Post: node encodings.  enc[b,idx,:] = softmax(hv_{idx-1} @ W_vert.T + b_vert)
// ---------------------------------------------------------------------------
__global__ __launch_bounds__(256) void k_enc(const float* __restrict__ Wv,
                                             const float* __restrict__ bv,
                                             float* __restrict__ out2) {
    int warp = threadIdx.x >> 5, lane = threadIdx.x & 31;
    int row = blockIdx.x * 8 + warp;       // b*S + idx, exact grid
    int b = row >> 4, idx = row & 15;
    const float* hv = g_hv + (idx * BB + b) * HH;   // slot idx = hv_{idx-1}
    float l[CC];
#pragma unroll
    for (int c = 0; c < CC; c++) l[c] = 0.f;
    for (int h = lane; h < HH; h += 32) {
        float v = hv[h];
#pragma unroll
        for (int c = 0; c < CC; c++) l[c] += v * Wv[c * HH + h];
    }
#pragma unroll
    for (int c = 0; c < CC; c++)
#pragma unroll
        for (int o = 16; o; o >>= 1) l[c] += __shfl_xor_sync(0xffffffffu, l[c], o);
    if (lane == 0) {
        float mx = -1e30f;
#pragma unroll
        for (int c = 0; c < CC; c++) { l[c] += bv[c]; mx = fmaxf(mx, l[c]); }
        float s = 0.f;
#pragma unroll
        for (int c = 0; c < CC; c++) { l[c] = expf(l[c] - mx); s += l[c]; }
        float inv = 1.f / s;
#pragma unroll
        for (int c = 0; c < CC; c++) out2[row * CC + c] = l[c] * inv;
    }
}

// ---------------------------------------------------------------------------
extern "C" void kernel_launch(void* const* d_in, const int* in_sizes, int n_in,
                              void* d_out, int out_size) {
    const float* z      = (const float*)d_in[0];
    const float* dep    = (const float*)d_in[1];
    const float* ne     = (const float*)d_in[2];
    const float* W_lin1 = (const float*)d_in[3];
    const float* b_lin1 = (const float*)d_in[4];
    const float* W_vert = (const float*)d_in[5];
    const float* b_vert = (const float*)d_in[6];
    const float* W_edge = (const float*)d_in[7];
    const float* b_edge = (const float*)d_in[8];
    const float* W_gate = (const float*)d_in[9];
    const float* b_gate = (const float*)d_in[10];
    const float* W_map  = (const float*)d_in[11];
    const float* b_map  = (const float*)d_in[12];
    const float* W_ih   = (const float*)d_in[13];
    const float* b_ih   = (const float*)d_in[14];
    const float* W_hh   = (const float*)d_in[15];
    const float* b_hh   = (const float*)d_in[16];
    float* out = (float*)d_out;

    // Opt-in to >48KB dynamic smem (idempotent attribute set; no allocation).
    static int attr_done = 0;
    if (!attr_done) {
        cudaFuncSetAttribute(k_gru,  cudaFuncAttributeMaxDynamicSharedMemorySize, GRU_SMEM);
        cudaFuncSetAttribute(k_agm,  cudaFuncAttributeMaxDynamicSharedMemorySize, AGM_SMEM);
        cudaFuncSetAttribute(k_lin1, cudaFuncAttributeMaxDynamicSharedMemorySize, LIN_SMEM);
        attr_done = 1;
    }

    dim3 gg((HH + BN - 1) / BN, BB / BM);   // (16, 8) = 128 CTAs = one wave

    k_lin1<<<gg, NT, LIN_SMEM>>>(z, W_lin1, b_lin1);                  // slot 0
    k_gru<<<gg, NT, GRU_SMEM>>>(0, 0, ne, W_ih, b_ih, W_hh, b_hh);    // hv_0
    for (int step = 1; step < SSZ; step++) {
        k_agm<<<gg, NT, AGM_SMEM>>>(step, dep, W_gate, b_gate, W_map, b_map);
        k_gru<<<gg, NT, GRU_SMEM>>>(step, 1, ne, W_ih, b_ih, W_hh, b_hh);
    }
    k_dots<<<(SSZ + 1) * BB / 8, 256>>>(W_edge);
    k_edges<<<BB * SSZ * SSZ / 256, 256>>>(b_edge, out);
    k_enc<<<BB * SSZ / 8, 256>>>(W_vert, b_vert, out + BB * SSZ * SSZ);
}

// round 16
// speedup vs baseline: 1.6964x; 1.1509x over previous
#include <cuda_runtime.h>
#include <math.h>

#define BB  512
#define SSZ 16
#define HH  501
#define CC  7

#define BK 32
#define NT 512          // 4 K-groups x 128 threads
#define KG 128
#define NTG 4
#define NGRP 4

// full-M kernels (lin1, step-0 GRU): BM=64
#define BM 64
#define BN 32
#define LDA_ 68
#define LDW_ 36
#define SA_SZ (BK * LDA_)
#define SW1_SZ (BK * LDW_)
#define SW3_SZ (3 * BK * LDW_)
#define GRU_SMEM (NGRP * (SA_SZ + SW3_SZ) * 4)   // 90112 B
#define LIN_SMEM (NGRP * (SA_SZ + SW1_SZ) * 4)   // 53248 B

// compacted kernels: BM2=32
#define BM2 32
#define LDA2 36
#define SA2_SZ (BK * LDA2)                       // 1152 floats
#define SW2_SZ (2 * BK * LDW_)                   // 2304
#define GRUC_SMEM (NGRP * (SA2_SZ + SW3_SZ) * 4) // 73728 B
#define AGMC_SMEM (NGRP * (SA2_SZ + SW2_SZ) * 4) // 55296 B

// Scratch (module-scope device globals; allocation-free per harness rules)
// g_hv slot i stores hv_{i-1}: slot 0 = graph_state0, slot idx+1 = hv_idx
__device__ float g_hv[(SSZ + 1) * BB * HH];
__device__ float g_hinc[BB * HH];                 // compacted h_in rows
__device__ float g_d1[(SSZ + 1) * BB];
__device__ float g_d2[(SSZ + 1) * BB];
__device__ float g_ghc[3 * HH];                   // c0 @ Whh.T
__device__ float g_outc[CC * HH];                 // 7 candidate GRU outputs
__device__ int   g_idx[SSZ * BB];                 // per-step active row lists
__device__ int   g_cnt[SSZ];

typedef unsigned long long u64;

__device__ __forceinline__ float sigf(float x) { return 1.0f / (1.0f + expf(-x)); }
__device__ __forceinline__ u64 pk2(float x, float y) {
    u64 r; asm("mov.b64 %0,{%1,%2};" : "=l"(r) : "f"(x), "f"(y)); return r;
}
__device__ __forceinline__ void fma2(u64& d, u64 a, u64 b) {
    asm("fma.rn.f32x2 %0,%1,%2,%0;" : "+l"(d) : "l"(a), "l"(b));
}
__device__ __forceinline__ void add2(u64& d, u64 a) {
    asm("add.rn.f32x2 %0,%1,%0;" : "+l"(d) : "l"(a));
}
__device__ __forceinline__ void up2(u64 v, float& a, float& b) {
    asm("mov.b64 {%0,%1},%2;" : "=f"(a), "=f"(b) : "l"(v));
}
#define GBAR(g) asm volatile("bar.sync %0, 128;" :: "r"(1 + (g)) : "memory")

// ===========================================================================
// k_gru_full: step-0 GRU over all 512 rows (h = graph_state0, slot 0).
// BM=64, split-K x4 (identical to R13 k_gru with use_hin=0, step=0).
// ===========================================================================
__global__ __launch_bounds__(NT) void k_gru_full(
        const float* __restrict__ ne,
        const float* __restrict__ Wih, const float* __restrict__ bih,
        const float* __restrict__ Whh, const float* __restrict__ bhh) {
    extern __shared__ __align__(16) float smemblk[];
    const int m0 = blockIdx.y * BM, n0 = blockIdx.x * BN;
    const int tid = threadIdx.x;
    const int g = tid >> 7, l = tid & 127;
    const int tx = l & 7, ty = l >> 3;
    const int n4 = tx * 4, m4 = ty * 4;
    const int kz = l & 31, r0 = l >> 5;
    const int kbase = g * KG;
    float* sA = smemblk + g * SA_SZ;
    float* sW = smemblk + NGRP * SA_SZ + g * SW3_SZ;
    const float* Hsrc = g_hv;

    u64 acc[3][4][2];
#pragma unroll
    for (int p = 0; p < 3; p++)
#pragma unroll
        for (int i = 0; i < 4; i++) { acc[p][i][0] = 0ull; acc[p][i][1] = 0ull; }

    float rAv[16], rWv[3][8];
    {
        int gk = kbase + kz;
#pragma unroll
        for (int i = 0; i < 16; i++)
            rAv[i] = Hsrc[(m0 + r0 + 4 * i) * HH + gk];
#pragma unroll
        for (int j = 0; j < 8; j++) {
            int r = r0 + 4 * j;
            bool ok = (n0 + r) < HH;
#pragma unroll
            for (int p = 0; p < 3; p++)
                rWv[p][j] = ok ? Whh[(p * HH + n0 + r) * HH + gk] : 0.f;
        }
    }

    for (int t = 0; t < NTG; t++) {
        GBAR(g);
#pragma unroll
        for (int i = 0; i < 16; i++) sA[kz * LDA_ + r0 + 4 * i] = rAv[i];
#pragma unroll
        for (int j = 0; j < 8; j++)
#pragma unroll
            for (int p = 0; p < 3; p++)
                sW[(p * BK + kz) * LDW_ + r0 + 4 * j] = rWv[p][j];
        GBAR(g);
        if (t + 1 < NTG) {
            int gk = kbase + (t + 1) * BK + kz;
            bool okk = gk < HH;
#pragma unroll
            for (int i = 0; i < 16; i++)
                rAv[i] = okk ? Hsrc[(m0 + r0 + 4 * i) * HH + gk] : 0.f;
#pragma unroll
            for (int j = 0; j < 8; j++) {
                int r = r0 + 4 * j;
                bool ok = okk && ((n0 + r) < HH);
#pragma unroll
                for (int p = 0; p < 3; p++)
                    rWv[p][j] = ok ? Whh[(p * HH + n0 + r) * HH + gk] : 0.f;
            }
        }
#pragma unroll
        for (int kk = 0; kk < BK; kk++) {
            float4 av = *reinterpret_cast<const float4*>(&sA[kk * LDA_ + m4]);
            u64 aa[4] = { pk2(av.x, av.x), pk2(av.y, av.y),
                          pk2(av.z, av.z), pk2(av.w, av.w) };
#pragma unroll
            for (int p = 0; p < 3; p++) {
                ulonglong2 wv = *reinterpret_cast<const ulonglong2*>(
                                    &sW[(p * BK + kk) * LDW_ + n4]);
#pragma unroll
                for (int im = 0; im < 4; im++) {
                    fma2(acc[p][im][0], aa[im], wv.x);
                    fma2(acc[p][im][1], aa[im], wv.y);
                }
            }
        }
    }

    u64* scratch = reinterpret_cast<u64*>(smemblk);
    __syncthreads();
    if (g > 0) {
        int c = 0;
#pragma unroll
        for (int p = 0; p < 3; p++)
#pragma unroll
            for (int im = 0; im < 4; im++)
#pragma unroll
                for (int h = 0; h < 2; h++) {
                    scratch[((g - 1) * 24 + c) * 128 + l] = acc[p][im][h]; c++;
                }
    }
    __syncthreads();
    if (g == 0) {
#pragma unroll
        for (int gi = 0; gi < 3; gi++) {
            int c = 0;
#pragma unroll
            for (int p = 0; p < 3; p++)
#pragma unroll
                for (int im = 0; im < 4; im++)
#pragma unroll
                    for (int h = 0; h < 2; h++) {
                        add2(acc[p][im][h], scratch[(gi * 24 + c) * 128 + l]); c++;
                    }
        }
        float af[3][4][4];
#pragma unroll
        for (int p = 0; p < 3; p++)
#pragma unroll
            for (int im = 0; im < 4; im++) {
                up2(acc[p][im][0], af[p][im][0], af[p][im][1]);
                up2(acc[p][im][1], af[p][im][2], af[p][im][3]);
            }
        float* O = g_hv + 1 * BB * HH;
#pragma unroll
        for (int im = 0; im < 4; im++) {
            int b = m0 + m4 + im;
            float x[CC];
#pragma unroll
            for (int c2 = 0; c2 < CC; c2++) x[c2] = ne[b * SSZ * CC + 0 * CC + c2];
#pragma unroll
            for (int jn = 0; jn < 4; jn++) {
                int n = n0 + n4 + jn;
                if (n >= HH) continue;
                float gir = bih[n], giz = bih[HH + n], gin = bih[2 * HH + n];
#pragma unroll
                for (int c2 = 0; c2 < CC; c2++) {
                    gir += x[c2] * Wih[n * CC + c2];
                    giz += x[c2] * Wih[(HH + n) * CC + c2];
                    gin += x[c2] * Wih[(2 * HH + n) * CC + c2];
                }
                float ghr = af[0][im][jn] + bhh[n];
                float ghz = af[1][im][jn] + bhh[HH + n];
                float ghn = af[2][im][jn] + bhh[2 * HH + n];
                float r  = sigf(gir + ghr);
                float zg = sigf(giz + ghz);
                float nv = tanhf(gin + r * ghn);
                float hp = Hsrc[b * HH + n];
                O[b * HH + n] = (1.f - zg) * nv + zg * hp;
            }
        }
    }
}

// ===========================================================================
// k_lin1 (once): g_hv[slot0] = z @ W_lin1.T + b_lin1, split-K x4, BM=64.
// ===========================================================================
__global__ __launch_bounds__(NT) void k_lin1(const float* __restrict__ A,
                                             const float* __restrict__ W,
                                             const float* __restrict__ bias) {
    extern __shared__ __align__(16) float smemblk[];
    const int m0 = blockIdx.y * BM, n0 = blockIdx.x * BN;
    const int tid = threadIdx.x;
    const int g = tid >> 7, l = tid & 127;
    const int tx = l & 7, ty = l >> 3;
    const int n4 = tx * 4, m4 = ty * 4;
    const int kz = l & 31, r0 = l >> 5;
    const int kbase = g * KG;
    float* sA = smemblk + g * SA_SZ;
    float* sW = smemblk + NGRP * SA_SZ + g * SW1_SZ;

    u64 acc[4][2];
#pragma unroll
    for (int i = 0; i < 4; i++) { acc[i][0] = 0ull; acc[i][1] = 0ull; }

    float rAv[16], rWv[8];
    {
        int gk = kbase + kz;
#pragma unroll
        for (int i = 0; i < 16; i++)
            rAv[i] = A[(m0 + r0 + 4 * i) * HH + gk];
#pragma unroll
        for (int j = 0; j < 8; j++) {
            int r = r0 + 4 * j;
            rWv[j] = ((n0 + r) < HH) ? W[(n0 + r) * HH + gk] : 0.f;
        }
    }

    for (int t = 0; t < NTG; t++) {
        GBAR(g);
#pragma unroll
        for (int i = 0; i < 16; i++) sA[kz * LDA_ + r0 + 4 * i] = rAv[i];
#pragma unroll
        for (int j = 0; j < 8; j++) sW[kz * LDW_ + r0 + 4 * j] = rWv[j];
        GBAR(g);
        if (t + 1 < NTG) {
            int gk = kbase + (t + 1) * BK + kz;
            bool okk = gk < HH;
#pragma unroll
            for (int i = 0; i < 16; i++)
                rAv[i] = okk ? A[(m0 + r0 + 4 * i) * HH + gk] : 0.f;
#pragma unroll
            for (int j = 0; j < 8; j++) {
                int r = r0 + 4 * j;
                rWv[j] = (okk && ((n0 + r) < HH)) ? W[(n0 + r) * HH + gk] : 0.f;
            }
        }
#pragma unroll
        for (int kk = 0; kk < BK; kk++) {
            float4 av = *reinterpret_cast<const float4*>(&sA[kk * LDA_ + m4]);
            u64 aa[4] = { pk2(av.x, av.x), pk2(av.y, av.y),
                          pk2(av.z, av.z), pk2(av.w, av.w) };
            ulonglong2 wv = *reinterpret_cast<const ulonglong2*>(&sW[kk * LDW_ + n4]);
#pragma unroll
            for (int im = 0; im < 4; im++) {
                fma2(acc[im][0], aa[im], wv.x);
                fma2(acc[im][1], aa[im], wv.y);
            }
        }
    }

    u64* scratch = reinterpret_cast<u64*>(smemblk);
    __syncthreads();
    if (g > 0) {
        int c = 0;
#pragma unroll
        for (int im = 0; im < 4; im++)
#pragma unroll
            for (int h = 0; h < 2; h++) {
                scratch[((g - 1) * 8 + c) * 128 + l] = acc[im][h]; c++;
            }
    }
    __syncthreads();
    if (g == 0) {
#pragma unroll
        for (int gi = 0; gi < 3; gi++) {
            int c = 0;
#pragma unroll
            for (int im = 0; im < 4; im++)
#pragma unroll
                for (int h = 0; h < 2; h++) {
                    add2(acc[im][h], scratch[(gi * 8 + c) * 128 + l]); c++;
                }
        }
#pragma unroll
        for (int im = 0; im < 4; im++) {
            float v0, v1, v2, v3;
            up2(acc[im][0], v0, v1);
            up2(acc[im][1], v2, v3);
            int b = m0 + m4 + im;
            float vv[4] = { v0, v1, v2, v3 };
#pragma unroll
            for (int jn = 0; jn < 4; jn++) {
                int n = n0 + n4 + jn;
                if (n < HH) g_hv[b * HH + n] = vv[jn] + bias[n];
            }
        }
    }
}

// ===========================================================================
// Precompute: ghc = c0 @ Whh.T  (c0[n] = 16*sig(bg[n])*bm[n]); warp per row.
// ===========================================================================
__global__ __launch_bounds__(256) void k_ghc(const float* __restrict__ Whh,
                                             const float* __restrict__ bg,
                                             const float* __restrict__ bm) {
    int row = blockIdx.x * 8 + (threadIdx.x >> 5);
    int lane = threadIdx.x & 31;
    if (row >= 3 * HH) return;
    float acc = 0.f;
    for (int k = lane; k < HH; k += 32) {
        float c0k = 16.0f * sigf(bg[k]) * bm[k];
        acc += c0k * Whh[row * HH + k];
    }
#pragma unroll
    for (int o = 16; o; o >>= 1) acc += __shfl_xor_sync(0xffffffffu, acc, o);
    if (lane == 0) g_ghc[row] = acc;
}

// ===========================================================================
// Precompute: outc[c][n] = GRU(x=onehot(c), h=c0)[n]   (step-independent)
// ===========================================================================
__global__ __launch_bounds__(512) void k_outc(
        const float* __restrict__ Wih, const float* __restrict__ bih,
        const float* __restrict__ bhh,
        const float* __restrict__ bg, const float* __restrict__ bm) {
    for (int i = threadIdx.x; i < CC * HH; i += 512) {
        int c = i / HH, n = i % HH;
        float c0n = 16.0f * sigf(bg[n]) * bm[n];
        float gir = Wih[n * CC + c] + bih[n];
        float giz = Wih[(HH + n) * CC + c] + bih[HH + n];
        float gin = Wih[(2 * HH + n) * CC + c] + bih[2 * HH + n];
        float ghr = g_ghc[n] + bhh[n];
        float ghz = g_ghc[HH + n] + bhh[HH + n];
        float ghn = g_ghc[2 * HH + n] + bhh[2 * HH + n];
        float r  = sigf(gir + ghr);
        float zg = sigf(giz + ghz);
        float nv = tanhf(gin + r * ghn);
        g_outc[c * HH + n] = (1.f - zg) * nv + zg * c0n;
    }
}

// ===========================================================================
// Compaction: per step s in 1..15, list of active rows (dep[b,s,s-1]=1) + cnt.
// Single CTA, 512 threads. Pads list to 512 entries with 0.
// ===========================================================================
__global__ __launch_bounds__(512) void k_compact(const float* __restrict__ dep) {
    __shared__ int cnt_s;
    int b = threadIdx.x;
    for (int s = 1; s < SSZ; s++) {
        if (b == 0) cnt_s = 0;
        __syncthreads();
        int pos = -1;
        if (dep[b * SSZ * SSZ + s * SSZ + (s - 1)] != 0.f)
            pos = atomicAdd(&cnt_s, 1);
        __syncthreads();
        if (pos >= 0) g_idx[s * BB + pos] = b;
        int c = cnt_s;
        if (b == 0) g_cnt[s] = c;
        if (b >= c) g_idx[s * BB + b] = 0;     // pad (valid row 0)
        __syncthreads();
    }
}

// ===========================================================================
// Fill: for every (s,b), s>=1, with mask=0: g_hv[slot s+1][b] = outc[class(b,s)]
// Warp per (s,b) row.
// ===========================================================================
__global__ __launch_bounds__(256) void k_fill(const float* __restrict__ dep,
                                              const float* __restrict__ ne) {
    int row = blockIdx.x * 8 + (threadIdx.x >> 5);   // 0 .. 15*512-1
    int lane = threadIdx.x & 31;
    int s = row / BB + 1, b = row % BB;
    if (dep[b * SSZ * SSZ + s * SSZ + (s - 1)] != 0.f) return;
    float cf = 0.f;
#pragma unroll
    for (int j = 0; j < CC; j++) cf += (float)j * ne[b * SSZ * CC + s * CC + j];
    int c = (int)(cf + 0.5f);
    float* O = g_hv + (s + 1) * BB * HH + b * HH;
    const float* src = g_outc + c * HH;
    for (int n = lane; n < HH; n += 32) O[n] = src[n];
}

// ===========================================================================
// k_agm_c: compacted aggregation (active rows only, no mask).
//   g_hinc[i,:] = 15*sig(bg)*bm + sig(hv@Wg.T+bg)*(hv@Wm.T+bm), hv = row idx[i]
// BM2=32, split-K x4, 2x4 microtile per 128-thread group.
// ===========================================================================
__global__ __launch_bounds__(NT) void k_agm_c(int step,
        const float* __restrict__ Wg, const float* __restrict__ bg,
        const float* __restrict__ Wm, const float* __restrict__ bm) {
    extern __shared__ __align__(16) float smemblk[];
    __shared__ int sidx[BM2];
    const int cnt = g_cnt[step];
    const int m0 = blockIdx.y * BM2;
    if (m0 >= cnt) return;
    const int n0 = blockIdx.x * BN;
    const int tid = threadIdx.x;
    const int g = tid >> 7, l = tid & 127;
    const int tx = l & 7, ty = l >> 3;
    const int n4 = tx * 4, m2 = ty * 2;
    const int kz = l & 31, r0 = l >> 5;
    const int kbase = g * KG;
    float* sA = smemblk + g * SA2_SZ;
    float* sW = smemblk + NGRP * SA2_SZ + g * SW2_SZ;
    const float* A = g_hv + step * BB * HH;

    if (tid < BM2) sidx[tid] = g_idx[step * BB + m0 + tid];
    __syncthreads();

    u64 acc[2][2][2];
#pragma unroll
    for (int p = 0; p < 2; p++)
#pragma unroll
        for (int i = 0; i < 2; i++) { acc[p][i][0] = 0ull; acc[p][i][1] = 0ull; }

    float rAv[8], rWv[2][8];
    {
        int gk = kbase + kz;
#pragma unroll
        for (int i = 0; i < 8; i++)
            rAv[i] = A[sidx[r0 + 4 * i] * HH + gk];
#pragma unroll
        for (int j = 0; j < 8; j++) {
            int r = r0 + 4 * j;
            bool ok = (n0 + r) < HH;
            rWv[0][j] = ok ? Wg[(n0 + r) * HH + gk] : 0.f;
            rWv[1][j] = ok ? Wm[(n0 + r) * HH + gk] : 0.f;
        }
    }

    for (int t = 0; t < NTG; t++) {
        GBAR(g);
#pragma unroll
        for (int i = 0; i < 8; i++) sA[kz * LDA2 + r0 + 4 * i] = rAv[i];
#pragma unroll
        for (int j = 0; j < 8; j++) {
            sW[kz * LDW_ + r0 + 4 * j] = rWv[0][j];
            sW[(BK + kz) * LDW_ + r0 + 4 * j] = rWv[1][j];
        }
        GBAR(g);
        if (t + 1 < NTG) {
            int gk = kbase + (t + 1) * BK + kz;
            bool okk = gk < HH;
#pragma unroll
            for (int i = 0; i < 8; i++)
                rAv[i] = okk ? A[sidx[r0 + 4 * i] * HH + gk] : 0.f;
#pragma unroll
            for (int j = 0; j < 8; j++) {
                int r = r0 + 4 * j;
                bool ok = okk && ((n0 + r) < HH);
                rWv[0][j] = ok ? Wg[(n0 + r) * HH + gk] : 0.f;
                rWv[1][j] = ok ? Wm[(n0 + r) * HH + gk] : 0.f;
            }
        }
#pragma unroll
        for (int kk = 0; kk < BK; kk++) {
            float2 av = *reinterpret_cast<const float2*>(&sA[kk * LDA2 + m2]);
            u64 aa0 = pk2(av.x, av.x), aa1 = pk2(av.y, av.y);
#pragma unroll
            for (int p = 0; p < 2; p++) {
                ulonglong2 wv = *reinterpret_cast<const ulonglong2*>(
                                    &sW[(p * BK + kk) * LDW_ + n4]);
                fma2(acc[p][0][0], aa0, wv.x);
                fma2(acc[p][0][1], aa0, wv.y);
                fma2(acc[p][1][0], aa1, wv.x);
                fma2(acc[p][1][1], aa1, wv.y);
            }
        }
    }

    u64* scratch = reinterpret_cast<u64*>(smemblk);
    __syncthreads();
    if (g > 0) {
        int c = 0;
#pragma unroll
        for (int p = 0; p < 2; p++)
#pragma unroll
            for (int im = 0; im < 2; im++)
#pragma unroll
                for (int h = 0; h < 2; h++) {
                    scratch[((g - 1) * 8 + c) * 128 + l] = acc[p][im][h]; c++;
                }
    }
    __syncthreads();
    if (g == 0) {
#pragma unroll
        for (int gi = 0; gi < 3; gi++) {
            int c = 0;
#pragma unroll
            for (int p = 0; p < 2; p++)
#pragma unroll
                for (int im = 0; im < 2; im++)
#pragma unroll
                    for (int h = 0; h < 2; h++) {
                        add2(acc[p][im][h], scratch[(gi * 8 + c) * 128 + l]); c++;
                    }
        }
        float af[2][2][4];
#pragma unroll
        for (int p = 0; p < 2; p++)
#pragma unroll
            for (int im = 0; im < 2; im++) {
                up2(acc[p][im][0], af[p][im][0], af[p][im][1]);
                up2(acc[p][im][1], af[p][im][2], af[p][im][3]);
            }
#pragma unroll
        for (int jn = 0; jn < 4; jn++) {
            int n = n0 + n4 + jn;
            if (n >= HH) continue;
            float bgv = bg[n], bmv = bm[n];
            float base = 15.0f * sigf(bgv) * bmv;
#pragma unroll
            for (int im = 0; im < 2; im++) {
                int i = m0 + m2 + im;      // unguarded: pad rows harmless
                float u = af[0][im][jn] + bgv;
                float v = af[1][im][jn] + bmv;
                g_hinc[i * HH + n] = base + sigf(u) * v;
            }
        }
    }
}

// ===========================================================================
// k_gru_c: compacted GRU: gh = g_hinc @ Whh.T (3 parts), scatter to hv slot.
// BM2=32, split-K x4, 2x4 microtile per group.
// ===========================================================================
__global__ __launch_bounds__(NT) void k_gru_c(int step,
        const float* __restrict__ ne,
        const float* __restrict__ Wih, const float* __restrict__ bih,
        const float* __restrict__ Whh, const float* __restrict__ bhh) {
    extern __shared__ __align__(16) float smemblk[];
    __shared__ int sidx[BM2];
    const int cnt = g_cnt[step];
    const int m0 = blockIdx.y * BM2;
    if (m0 >= cnt) return;
    const int n0 = blockIdx.x * BN;
    const int tid = threadIdx.x;
    const int g = tid >> 7, l = tid & 127;
    const int tx = l & 7, ty = l >> 3;
    const int n4 = tx * 4, m2 = ty * 2;
    const int kz = l & 31, r0 = l >> 5;
    const int kbase = g * KG;
    float* sA = smemblk + g * SA2_SZ;
    float* sW = smemblk + NGRP * SA2_SZ + g * SW3_SZ;
    const float* Hsrc = g_hinc;

    if (tid < BM2) sidx[tid] = g_idx[step * BB + m0 + tid];
    __syncthreads();

    u64 acc[3][2][2];
#pragma unroll
    for (int p = 0; p < 3; p++)
#pragma unroll
        for (int i = 0; i < 2; i++) { acc[p][i][0] = 0ull; acc[p][i][1] = 0ull; }

    float rAv[8], rWv[3][8];
    {
        int gk = kbase + kz;
#pragma unroll
        for (int i = 0; i < 8; i++)
            rAv[i] = Hsrc[(m0 + r0 + 4 * i) * HH + gk];
#pragma unroll
        for (int j = 0; j < 8; j++) {
            int r = r0 + 4 * j;
            bool ok = (n0 + r) < HH;
#pragma unroll
            for (int p = 0; p < 3; p++)
                rWv[p][j] = ok ? Whh[(p * HH + n0 + r) * HH + gk] : 0.f;
        }
    }

    for (int t = 0; t < NTG; t++) {
        GBAR(g);
#pragma unroll
        for (int i = 0; i < 8; i++) sA[kz * LDA2 + r0 + 4 * i] = rAv[i];
#pragma unroll
        for (int j = 0; j < 8; j++)
#pragma unroll
            for (int p = 0; p < 3; p++)
                sW[(p * BK + kz) * LDW_ + r0 + 4 * j] = rWv[p][j];
        GBAR(g);
        if (t + 1 < NTG) {
            int gk = kbase + (t + 1) * BK + kz;
            bool okk = gk < HH;
#pragma unroll
            for (int i = 0; i < 8; i++)
                rAv[i] = okk ? Hsrc[(m0 + r0 + 4 * i) * HH + gk] : 0.f;
#pragma unroll
            for (int j = 0; j < 8; j++) {
                int r = r0 + 4 * j;
                bool ok = okk && ((n0 + r) < HH);
#pragma unroll
                for (int p = 0; p < 3; p++)
                    rWv[p][j] = ok ? Whh[(p * HH + n0 + r) * HH + gk] : 0.f;
            }
        }
#pragma unroll
        for (int kk = 0; kk < BK; kk++) {
            float2 av = *reinterpret_cast<const float2*>(&sA[kk * LDA2 + m2]);
            u64 aa0 = pk2(av.x, av.x), aa1 = pk2(av.y, av.y);
#pragma unroll
            for (int p = 0; p < 3; p++) {
                ulonglong2 wv = *reinterpret_cast<const ulonglong2*>(
                                    &sW[(p * BK + kk) * LDW_ + n4]);
                fma2(acc[p][0][0], aa0, wv.x);
                fma2(acc[p][0][1], aa0, wv.y);
                fma2(acc[p][1][0], aa1, wv.x);
                fma2(acc[p][1][1], aa1, wv.y);
            }
        }
    }

    u64* scratch = reinterpret_cast<u64*>(smemblk);
    __syncthreads();
    if (g > 0) {
        int c = 0;
#pragma unroll
        for (int p = 0; p < 3; p++)
#pragma unroll
            for (int im = 0; im < 2; im++)
#pragma unroll
                for (int h = 0; h < 2; h++) {
                    scratch[((g - 1) * 12 + c) * 128 + l] = acc[p][im][h]; c++;
                }
    }
    __syncthreads();
    if (g == 0) {
#pragma unroll
        for (int gi = 0; gi < 3; gi++) {
            int c = 0;
#pragma unroll
            for (int p = 0; p < 3; p++)
#pragma unroll
                for (int im = 0; im < 2; im++)
#pragma unroll
                    for (int h = 0; h < 2; h++) {
                        add2(acc[p][im][h], scratch[(gi * 12 + c) * 128 + l]); c++;
                    }
        }
        float af[3][2][4];
#pragma unroll
        for (int p = 0; p < 3; p++)
#pragma unroll
            for (int im = 0; im < 2; im++) {
                up2(acc[p][im][0], af[p][im][0], af[p][im][1]);
                up2(acc[p][im][1], af[p][im][2], af[p][im][3]);
            }
        float* O = g_hv + (step + 1) * BB * HH;
#pragma unroll
        for (int im = 0; im < 2; im++) {
            int i = m0 + m2 + im;
            if (i >= cnt) continue;
            int b = sidx[m2 + im];
            float x[CC];
#pragma unroll
            for (int c2 = 0; c2 < CC; c2++) x[c2] = ne[b * SSZ * CC + step * CC + c2];
#pragma unroll
            for (int jn = 0; jn < 4; jn++) {
                int n = n0 + n4 + jn;
                if (n >= HH) continue;
                float gir = bih[n], giz = bih[HH + n], gin = bih[2 * HH + n];
#pragma unroll
                for (int c2 = 0; c2 < CC; c2++) {
                    gir += x[c2] * Wih[n * CC + c2];
                    giz += x[c2] * Wih[(HH + n) * CC + c2];
                    gin += x[c2] * Wih[(2 * HH + n) * CC + c2];
                }
                float ghr = af[0][im][jn] + bhh[n];
                float ghz = af[1][im][jn] + bhh[HH + n];
                float ghn = af[2][im][jn] + bhh[2 * HH + n];
                float r  = sigf(gir + ghr);
                float zg = sigf(giz + ghz);
                float nv = tanhf(gin + r * ghn);
                float hp = Hsrc[i * HH + n];
                O[b * HH + n] = (1.f - zg) * nv + zg * hp;
            }
        }
    }
}

// ---------------------------------------------------------------------------
// Post: edge-logit dot products  d1[i]=w1.hv_i  d2[i]=w2.hv_i  (warp per row)
// ---------------------------------------------------------------------------
__global__ __launch_bounds__(256) void k_dots(const float* __restrict__ We) {
    int warp = threadIdx.x >> 5, lane = threadIdx.x & 31;
    int row = blockIdx.x * 8 + warp;
    const float* hv = g_hv + row * HH;
    float a1 = 0.f, a2 = 0.f;
    for (int h = lane; h < HH; h += 32) {
        float v = hv[h];
        a1 += v * We[h];
        a2 += v * We[HH + h];
    }
#pragma unroll
    for (int o = 16; o; o >>= 1) {
        a1 += __shfl_xor_sync(0xffffffffu, a1, o);
        a2 += __shfl_xor_sync(0xffffffffu, a2, o);
    }
    if (lane == 0) { g_d1[row] = a1; g_d2[row] = a2; }
}

// ---------------------------------------------------------------------------
// Post: generated dep graph (hard threshold sigmoid(x)>=0.5 <=> x>=0)
// ---------------------------------------------------------------------------
__global__ void k_edges(const float* __restrict__ be_p, float* __restrict__ out) {
    int gid = blockIdx.x * blockDim.x + threadIdx.x;
    int j = gid & 15, idx = (gid >> 4) & 15, b = gid >> 8;
    float val = 0.f;
    if (idx > 0 && j < idx) {
        float t;
        if (j == idx - 1) t = g_d1[idx * BB + b] + g_d2[idx * BB + b];
        else              t = g_d1[(idx + 1) * BB + b] + g_d2[(j + 1) * BB + b];
        t += be_p[0];
        val = (t >= 0.f) ? 1.f : 0.f;
    }
    out[gid] = val;
}

// ---------------------------------------------------------------------------
// Post: node encodings.  enc[b,idx,:] = softmax(hv_{idx-1} @ W_vert.T + b_vert)
// ---------------------------------------------------------------------------
__global__ __launch_bounds__(256) void k_enc(const float* __restrict__ Wv,
                                             const float* __restrict__ bv,
                                             float* __restrict__ out2) {
    int warp = threadIdx.x >> 5, lane = threadIdx.x & 31;
    int row = blockIdx.x * 8 + warp;
    int b = row >> 4, idx = row & 15;
    const float* hv = g_hv + (idx * BB + b) * HH;
    float l[CC];
#pragma unroll
    for (int c = 0; c < CC; c++) l[c] = 0.f;
    for (int h = lane; h < HH; h += 32) {
        float v = hv[h];
#pragma unroll
        for (int c = 0; c < CC; c++) l[c] += v * Wv[c * HH + h];
    }
#pragma unroll
    for (int c = 0; c < CC; c++)
#pragma unroll
        for (int o = 16; o; o >>= 1) l[c] += __shfl_xor_sync(0xffffffffu, l[c], o);
    if (lane == 0) {
        float mx = -1e30f;
#pragma unroll
        for (int c = 0; c < CC; c++) { l[c] += bv[c]; mx = fmaxf(mx, l[c]); }
        float s = 0.f;
#pragma unroll
        for (int c = 0; c < CC; c++) { l[c] = expf(l[c] - mx); s += l[c]; }
        float inv = 1.f / s;
#pragma unroll
        for (int c = 0; c < CC; c++) out2[row * CC + c] = l[c] * inv;
    }
}

// ---------------------------------------------------------------------------
extern "C" void kernel_launch(void* const* d_in, const int* in_sizes, int n_in,
                              void* d_out, int out_size) {
    const float* z      = (const float*)d_in[0];
    const float* dep    = (const float*)d_in[1];
    const float* ne     = (const float*)d_in[2];
    const float* W_lin1 = (const float*)d_in[3];
    const float* b_lin1 = (const float*)d_in[4];
    const float* W_vert = (const float*)d_in[5];
    const float* b_vert = (const float*)d_in[6];
    const float* W_edge = (const float*)d_in[7];
    const float* b_edge = (const float*)d_in[8];
    const float* W_gate = (const float*)d_in[9];
    const float* b_gate = (const float*)d_in[10];
    const float* W_map  = (const float*)d_in[11];
    const float* b_map  = (const float*)d_in[12];
    const float* W_ih   = (const float*)d_in[13];
    const float* b_ih   = (const float*)d_in[14];
    const float* W_hh   = (const float*)d_in[15];
    const float* b_hh   = (const float*)d_in[16];
    float* out = (float*)d_out;

    static int attr_done = 0;
    if (!attr_done) {
        cudaFuncSetAttribute(k_gru_full, cudaFuncAttributeMaxDynamicSharedMemorySize, GRU_SMEM);
        cudaFuncSetAttribute(k_lin1,  cudaFuncAttributeMaxDynamicSharedMemorySize, LIN_SMEM);
        cudaFuncSetAttribute(k_gru_c, cudaFuncAttributeMaxDynamicSharedMemorySize, GRUC_SMEM);
        cudaFuncSetAttribute(k_agm_c, cudaFuncAttributeMaxDynamicSharedMemorySize, AGMC_SMEM);
        attr_done = 1;
    }

    dim3 ggF(16, BB / BM);      // full-M kernels: (16, 8)
    dim3 ggC(16, BB / BM2);     // compacted kernels: (16, 16), early-exit by cnt

    k_lin1<<<ggF, NT, LIN_SMEM>>>(z, W_lin1, b_lin1);             // slot 0
    k_ghc<<<(3 * HH + 7) / 8, 256>>>(W_hh, b_gate, b_map);        // ghc
    k_outc<<<1, 512>>>(W_ih, b_ih, b_hh, b_gate, b_map);          // outc table
    k_compact<<<1, 512>>>(dep);                                    // active lists
    k_fill<<<(SSZ - 1) * BB / 8, 256>>>(dep, ne);                 // inactive fills
    k_gru_full<<<ggF, NT, GRU_SMEM>>>(ne, W_ih, b_ih, W_hh, b_hh);// hv_0 (all rows)
    for (int step = 1; step < SSZ; step++) {
        k_agm_c<<<ggC, NT, AGMC_SMEM>>>(step, W_gate, b_gate, W_map, b_map);
        k_gru_c<<<ggC, NT, GRUC_SMEM>>>(step, ne, W_ih, b_ih, W_hh, b_hh);
    }
    k_dots<<<(SSZ + 1) * BB / 8, 256>>>(W_edge);
    k_edges<<<BB * SSZ * SSZ / 256, 256>>>(b_edge, out);
    k_enc<<<BB * SSZ / 8, 256>>>(W_vert, b_vert, out + BB * SSZ * SSZ);
}

// round 17
// speedup vs baseline: 1.7520x; 1.0328x over previous
#include <cuda_runtime.h>
#include <math.h>

#define BB  512
#define SSZ 16
#define HH  501
#define CC  7

#define BK 32
#define NT 512          // 4 K-groups x 128 threads
#define KG 128
#define NTG 4
#define NGRP 4

// full-M kernels (lin1, step-0 GRU): BM=64
#define BM 64
#define BN 32
#define LDA_ 68
#define LDW_ 36
#define SA_SZ (BK * LDA_)
#define SW1_SZ (BK * LDW_)
#define SW3_SZ (3 * BK * LDW_)
#define GRU_SMEM (NGRP * (SA_SZ + SW3_SZ) * 4)   // 90112 B
#define LIN_SMEM (NGRP * (SA_SZ + SW1_SZ) * 4)   // 53248 B

// compacted kernels: BM2=32
#define BM2 32
#define LDA2 36
#define SA2_SZ (BK * LDA2)                       // 1152 floats
#define SW2_SZ (2 * BK * LDW_)                   // 2304
#define GRUC_SMEM (NGRP * (SA2_SZ + SW3_SZ) * 4) // 73728 B
#define AGMC_SMEM (NGRP * (SA2_SZ + SW2_SZ) * 4) // 55296 B

#define NDOTS ((SSZ + 1) * BB)   // 8704 rows for dots
#define NENC  (SSZ * BB)         // 8192 rows for enc

// Scratch (module-scope device globals; allocation-free per harness rules)
// g_hv slot i stores hv_{i-1}: slot 0 = graph_state0, slot idx+1 = hv_idx
__device__ float g_hv[(SSZ + 1) * BB * HH];
__device__ float g_hinc[BB * HH];                 // compacted h_in rows
__device__ float g_d1[(SSZ + 1) * BB];
__device__ float g_d2[(SSZ + 1) * BB];
__device__ float g_ghc[3 * HH];                   // c0 @ Whh.T
__device__ float g_outc[CC * HH];                 // 7 candidate GRU outputs
__device__ int   g_idx[SSZ * BB];                 // per-step active row lists
__device__ int   g_cnt[SSZ];

typedef unsigned long long u64;

__device__ __forceinline__ float sigf(float x) { return 1.0f / (1.0f + expf(-x)); }
__device__ __forceinline__ u64 pk2(float x, float y) {
    u64 r; asm("mov.b64 %0,{%1,%2};" : "=l"(r) : "f"(x), "f"(y)); return r;
}
__device__ __forceinline__ void fma2(u64& d, u64 a, u64 b) {
    asm("fma.rn.f32x2 %0,%1,%2,%0;" : "+l"(d) : "l"(a), "l"(b));
}
__device__ __forceinline__ void add2(u64& d, u64 a) {
    asm("add.rn.f32x2 %0,%1,%0;" : "+l"(d) : "l"(a));
}
__device__ __forceinline__ void up2(u64 v, float& a, float& b) {
    asm("mov.b64 {%0,%1},%2;" : "=f"(a), "=f"(b) : "l"(v));
}
#define GBAR(g) asm volatile("bar.sync %0, 128;" :: "r"(1 + (g)) : "memory")

// ===========================================================================
// k_gru_full: step-0 GRU over all 512 rows (h = graph_state0, slot 0).
// BM=64, split-K x4.
// ===========================================================================
__global__ __launch_bounds__(NT) void k_gru_full(
        const float* __restrict__ ne,
        const float* __restrict__ Wih, const float* __restrict__ bih,
        const float* __restrict__ Whh, const float* __restrict__ bhh) {
    extern __shared__ __align__(16) float smemblk[];
    const int m0 = blockIdx.y * BM, n0 = blockIdx.x * BN;
    const int tid = threadIdx.x;
    const int g = tid >> 7, l = tid & 127;
    const int tx = l & 7, ty = l >> 3;
    const int n4 = tx * 4, m4 = ty * 4;
    const int kz = l & 31, r0 = l >> 5;
    const int kbase = g * KG;
    float* sA = smemblk + g * SA_SZ;
    float* sW = smemblk + NGRP * SA_SZ + g * SW3_SZ;
    const float* Hsrc = g_hv;

    u64 acc[3][4][2];
#pragma unroll
    for (int p = 0; p < 3; p++)
#pragma unroll
        for (int i = 0; i < 4; i++) { acc[p][i][0] = 0ull; acc[p][i][1] = 0ull; }

    float rAv[16], rWv[3][8];
    {
        int gk = kbase + kz;
#pragma unroll
        for (int i = 0; i < 16; i++)
            rAv[i] = Hsrc[(m0 + r0 + 4 * i) * HH + gk];
#pragma unroll
        for (int j = 0; j < 8; j++) {
            int r = r0 + 4 * j;
            bool ok = (n0 + r) < HH;
#pragma unroll
            for (int p = 0; p < 3; p++)
                rWv[p][j] = ok ? Whh[(p * HH + n0 + r) * HH + gk] : 0.f;
        }
    }

    for (int t = 0; t < NTG; t++) {
        GBAR(g);
#pragma unroll
        for (int i = 0; i < 16; i++) sA[kz * LDA_ + r0 + 4 * i] = rAv[i];
#pragma unroll
        for (int j = 0; j < 8; j++)
#pragma unroll
            for (int p = 0; p < 3; p++)
                sW[(p * BK + kz) * LDW_ + r0 + 4 * j] = rWv[p][j];
        GBAR(g);
        if (t + 1 < NTG) {
            int gk = kbase + (t + 1) * BK + kz;
            bool okk = gk < HH;
#pragma unroll
            for (int i = 0; i < 16; i++)
                rAv[i] = okk ? Hsrc[(m0 + r0 + 4 * i) * HH + gk] : 0.f;
#pragma unroll
            for (int j = 0; j < 8; j++) {
                int r = r0 + 4 * j;
                bool ok = okk && ((n0 + r) < HH);
#pragma unroll
                for (int p = 0; p < 3; p++)
                    rWv[p][j] = ok ? Whh[(p * HH + n0 + r) * HH + gk] : 0.f;
            }
        }
#pragma unroll
        for (int kk = 0; kk < BK; kk++) {
            float4 av = *reinterpret_cast<const float4*>(&sA[kk * LDA_ + m4]);
            u64 aa[4] = { pk2(av.x, av.x), pk2(av.y, av.y),
                          pk2(av.z, av.z), pk2(av.w, av.w) };
#pragma unroll
            for (int p = 0; p < 3; p++) {
                ulonglong2 wv = *reinterpret_cast<const ulonglong2*>(
                                    &sW[(p * BK + kk) * LDW_ + n4]);
#pragma unroll
                for (int im = 0; im < 4; im++) {
                    fma2(acc[p][im][0], aa[im], wv.x);
                    fma2(acc[p][im][1], aa[im], wv.y);
                }
            }
        }
    }

    u64* scratch = reinterpret_cast<u64*>(smemblk);
    __syncthreads();
    if (g > 0) {
        int c = 0;
#pragma unroll
        for (int p = 0; p < 3; p++)
#pragma unroll
            for (int im = 0; im < 4; im++)
#pragma unroll
                for (int h = 0; h < 2; h++) {
                    scratch[((g - 1) * 24 + c) * 128 + l] = acc[p][im][h]; c++;
                }
    }
    __syncthreads();
    if (g == 0) {
#pragma unroll
        for (int gi = 0; gi < 3; gi++) {
            int c = 0;
#pragma unroll
            for (int p = 0; p < 3; p++)
#pragma unroll
                for (int im = 0; im < 4; im++)
#pragma unroll
                    for (int h = 0; h < 2; h++) {
                        add2(acc[p][im][h], scratch[(gi * 24 + c) * 128 + l]); c++;
                    }
        }
        float af[3][4][4];
#pragma unroll
        for (int p = 0; p < 3; p++)
#pragma unroll
            for (int im = 0; im < 4; im++) {
                up2(acc[p][im][0], af[p][im][0], af[p][im][1]);
                up2(acc[p][im][1], af[p][im][2], af[p][im][3]);
            }
        float* O = g_hv + 1 * BB * HH;
#pragma unroll
        for (int im = 0; im < 4; im++) {
            int b = m0 + m4 + im;
            float x[CC];
#pragma unroll
            for (int c2 = 0; c2 < CC; c2++) x[c2] = ne[b * SSZ * CC + 0 * CC + c2];
#pragma unroll
            for (int jn = 0; jn < 4; jn++) {
                int n = n0 + n4 + jn;
                if (n >= HH) continue;
                float gir = bih[n], giz = bih[HH + n], gin = bih[2 * HH + n];
#pragma unroll
                for (int c2 = 0; c2 < CC; c2++) {
                    gir += x[c2] * Wih[n * CC + c2];
                    giz += x[c2] * Wih[(HH + n) * CC + c2];
                    gin += x[c2] * Wih[(2 * HH + n) * CC + c2];
                }
                float ghr = af[0][im][jn] + bhh[n];
                float ghz = af[1][im][jn] + bhh[HH + n];
                float ghn = af[2][im][jn] + bhh[2 * HH + n];
                float r  = sigf(gir + ghr);
                float zg = sigf(giz + ghz);
                float nv = tanhf(gin + r * ghn);
                float hp = Hsrc[b * HH + n];
                O[b * HH + n] = (1.f - zg) * nv + zg * hp;
            }
        }
    }
}

// ===========================================================================
// k_lin1 (once): g_hv[slot0] = z @ W_lin1.T + b_lin1, split-K x4, BM=64.
// ===========================================================================
__global__ __launch_bounds__(NT) void k_lin1(const float* __restrict__ A,
                                             const float* __restrict__ W,
                                             const float* __restrict__ bias) {
    extern __shared__ __align__(16) float smemblk[];
    const int m0 = blockIdx.y * BM, n0 = blockIdx.x * BN;
    const int tid = threadIdx.x;
    const int g = tid >> 7, l = tid & 127;
    const int tx = l & 7, ty = l >> 3;
    const int n4 = tx * 4, m4 = ty * 4;
    const int kz = l & 31, r0 = l >> 5;
    const int kbase = g * KG;
    float* sA = smemblk + g * SA_SZ;
    float* sW = smemblk + NGRP * SA_SZ + g * SW1_SZ;

    u64 acc[4][2];
#pragma unroll
    for (int i = 0; i < 4; i++) { acc[i][0] = 0ull; acc[i][1] = 0ull; }

    float rAv[16], rWv[8];
    {
        int gk = kbase + kz;
#pragma unroll
        for (int i = 0; i < 16; i++)
            rAv[i] = A[(m0 + r0 + 4 * i) * HH + gk];
#pragma unroll
        for (int j = 0; j < 8; j++) {
            int r = r0 + 4 * j;
            rWv[j] = ((n0 + r) < HH) ? W[(n0 + r) * HH + gk] : 0.f;
        }
    }

    for (int t = 0; t < NTG; t++) {
        GBAR(g);
#pragma unroll
        for (int i = 0; i < 16; i++) sA[kz * LDA_ + r0 + 4 * i] = rAv[i];
#pragma unroll
        for (int j = 0; j < 8; j++) sW[kz * LDW_ + r0 + 4 * j] = rWv[j];
        GBAR(g);
        if (t + 1 < NTG) {
            int gk = kbase + (t + 1) * BK + kz;
            bool okk = gk < HH;
#pragma unroll
            for (int i = 0; i < 16; i++)
                rAv[i] = okk ? A[(m0 + r0 + 4 * i) * HH + gk] : 0.f;
#pragma unroll
            for (int j = 0; j < 8; j++) {
                int r = r0 + 4 * j;
                rWv[j] = (okk && ((n0 + r) < HH)) ? W[(n0 + r) * HH + gk] : 0.f;
            }
        }
#pragma unroll
        for (int kk = 0; kk < BK; kk++) {
            float4 av = *reinterpret_cast<const float4*>(&sA[kk * LDA_ + m4]);
            u64 aa[4] = { pk2(av.x, av.x), pk2(av.y, av.y),
                          pk2(av.z, av.z), pk2(av.w, av.w) };
            ulonglong2 wv = *reinterpret_cast<const ulonglong2*>(&sW[kk * LDW_ + n4]);
#pragma unroll
            for (int im = 0; im < 4; im++) {
                fma2(acc[im][0], aa[im], wv.x);
                fma2(acc[im][1], aa[im], wv.y);
            }
        }
    }

    u64* scratch = reinterpret_cast<u64*>(smemblk);
    __syncthreads();
    if (g > 0) {
        int c = 0;
#pragma unroll
        for (int im = 0; im < 4; im++)
#pragma unroll
            for (int h = 0; h < 2; h++) {
                scratch[((g - 1) * 8 + c) * 128 + l] = acc[im][h]; c++;
            }
    }
    __syncthreads();
    if (g == 0) {
#pragma unroll
        for (int gi = 0; gi < 3; gi++) {
            int c = 0;
#pragma unroll
            for (int im = 0; im < 4; im++)
#pragma unroll
                for (int h = 0; h < 2; h++) {
                    add2(acc[im][h], scratch[(gi * 8 + c) * 128 + l]); c++;
                }
        }
#pragma unroll
        for (int im = 0; im < 4; im++) {
            float v0, v1, v2, v3;
            up2(acc[im][0], v0, v1);
            up2(acc[im][1], v2, v3);
            int b = m0 + m4 + im;
            float vv[4] = { v0, v1, v2, v3 };
#pragma unroll
            for (int jn = 0; jn < 4; jn++) {
                int n = n0 + n4 + jn;
                if (n < HH) g_hv[b * HH + n] = vv[jn] + bias[n];
            }
        }
    }
}

// ===========================================================================
// Precompute: ghc = c0 @ Whh.T  (c0[n] = 16*sig(bg[n])*bm[n]); warp per row.
// ===========================================================================
__global__ __launch_bounds__(256) void k_ghc(const float* __restrict__ Whh,
                                             const float* __restrict__ bg,
                                             const float* __restrict__ bm) {
    int row = blockIdx.x * 8 + (threadIdx.x >> 5);
    int lane = threadIdx.x & 31;
    if (row >= 3 * HH) return;
    float acc = 0.f;
    for (int k = lane; k < HH; k += 32) {
        float c0k = 16.0f * sigf(bg[k]) * bm[k];
        acc += c0k * Whh[row * HH + k];
    }
#pragma unroll
    for (int o = 16; o; o >>= 1) acc += __shfl_xor_sync(0xffffffffu, acc, o);
    if (lane == 0) g_ghc[row] = acc;
}

// ===========================================================================
// Precompute: outc[c][n] = GRU(x=onehot(c), h=c0)[n]   (step-independent)
// ===========================================================================
__global__ __launch_bounds__(512) void k_outc(
        const float* __restrict__ Wih, const float* __restrict__ bih,
        const float* __restrict__ bhh,
        const float* __restrict__ bg, const float* __restrict__ bm) {
    for (int i = threadIdx.x; i < CC * HH; i += 512) {
        int c = i / HH, n = i % HH;
        float c0n = 16.0f * sigf(bg[n]) * bm[n];
        float gir = Wih[n * CC + c] + bih[n];
        float giz = Wih[(HH + n) * CC + c] + bih[HH + n];
        float gin = Wih[(2 * HH + n) * CC + c] + bih[2 * HH + n];
        float ghr = g_ghc[n] + bhh[n];
        float ghz = g_ghc[HH + n] + bhh[HH + n];
        float ghn = g_ghc[2 * HH + n] + bhh[2 * HH + n];
        float r  = sigf(gir + ghr);
        float zg = sigf(giz + ghz);
        float nv = tanhf(gin + r * ghn);
        g_outc[c * HH + n] = (1.f - zg) * nv + zg * c0n;
    }
}

// ===========================================================================
// Parallel compaction: warp w handles step w+1; ballot prefix-scan.
// One block, 480 threads (15 full warps).
// ===========================================================================
__global__ __launch_bounds__(480) void k_compact_par(const float* __restrict__ dep) {
    int w = threadIdx.x >> 5, lane = threadIdx.x & 31;
    int s = w + 1;
    int total = 0;
#pragma unroll
    for (int c = 0; c < 16; c++) {
        int b = c * 32 + lane;
        bool act = dep[b * SSZ * SSZ + s * SSZ + (s - 1)] != 0.f;
        unsigned bal = __ballot_sync(0xffffffffu, act);
        int pos = total + __popc(bal & ((1u << lane) - 1u));
        if (act) g_idx[s * BB + pos] = b;
        total += __popc(bal);
    }
    for (int i = total + lane; i < BB; i += 32) g_idx[s * BB + i] = 0;  // pad
    if (lane == 0) g_cnt[s] = total;
}

// ===========================================================================
// Fill: for every (s,b), s>=1, with mask=0: g_hv[slot s+1][b] = outc[class(b,s)]
// Warp per (s,b) row.
// ===========================================================================
__global__ __launch_bounds__(256) void k_fill(const float* __restrict__ dep,
                                              const float* __restrict__ ne) {
    int row = blockIdx.x * 8 + (threadIdx.x >> 5);   // 0 .. 15*512-1
    int lane = threadIdx.x & 31;
    int s = row / BB + 1, b = row % BB;
    if (dep[b * SSZ * SSZ + s * SSZ + (s - 1)] != 0.f) return;
    float cf = 0.f;
#pragma unroll
    for (int j = 0; j < CC; j++) cf += (float)j * ne[b * SSZ * CC + s * CC + j];
    int c = (int)(cf + 0.5f);
    float* O = g_hv + (s + 1) * BB * HH + b * HH;
    const float* src = g_outc + c * HH;
    for (int n = lane; n < HH; n += 32) O[n] = src[n];
}

// ===========================================================================
// k_agm_c: compacted aggregation (active rows only, no mask).
// ===========================================================================
__global__ __launch_bounds__(NT) void k_agm_c(int step,
        const float* __restrict__ Wg, const float* __restrict__ bg,
        const float* __restrict__ Wm, const float* __restrict__ bm) {
    extern __shared__ __align__(16) float smemblk[];
    __shared__ int sidx[BM2];
    const int cnt = g_cnt[step];
    const int m0 = blockIdx.y * BM2;
    if (m0 >= cnt) return;
    const int n0 = blockIdx.x * BN;
    const int tid = threadIdx.x;
    const int g = tid >> 7, l = tid & 127;
    const int tx = l & 7, ty = l >> 3;
    const int n4 = tx * 4, m2 = ty * 2;
    const int kz = l & 31, r0 = l >> 5;
    const int kbase = g * KG;
    float* sA = smemblk + g * SA2_SZ;
    float* sW = smemblk + NGRP * SA2_SZ + g * SW2_SZ;
    const float* A = g_hv + step * BB * HH;

    if (tid < BM2) sidx[tid] = g_idx[step * BB + m0 + tid];
    __syncthreads();

    u64 acc[2][2][2];
#pragma unroll
    for (int p = 0; p < 2; p++)
#pragma unroll
        for (int i = 0; i < 2; i++) { acc[p][i][0] = 0ull; acc[p][i][1] = 0ull; }

    float rAv[8], rWv[2][8];
    {
        int gk = kbase + kz;
#pragma unroll
        for (int i = 0; i < 8; i++)
            rAv[i] = A[sidx[r0 + 4 * i] * HH + gk];
#pragma unroll
        for (int j = 0; j < 8; j++) {
            int r = r0 + 4 * j;
            bool ok = (n0 + r) < HH;
            rWv[0][j] = ok ? Wg[(n0 + r) * HH + gk] : 0.f;
            rWv[1][j] = ok ? Wm[(n0 + r) * HH + gk] : 0.f;
        }
    }

    for (int t = 0; t < NTG; t++) {
        GBAR(g);
#pragma unroll
        for (int i = 0; i < 8; i++) sA[kz * LDA2 + r0 + 4 * i] = rAv[i];
#pragma unroll
        for (int j = 0; j < 8; j++) {
            sW[kz * LDW_ + r0 + 4 * j] = rWv[0][j];
            sW[(BK + kz) * LDW_ + r0 + 4 * j] = rWv[1][j];
        }
        GBAR(g);
        if (t + 1 < NTG) {
            int gk = kbase + (t + 1) * BK + kz;
            bool okk = gk < HH;
#pragma unroll
            for (int i = 0; i < 8; i++)
                rAv[i] = okk ? A[sidx[r0 + 4 * i] * HH + gk] : 0.f;
#pragma unroll
            for (int j = 0; j < 8; j++) {
                int r = r0 + 4 * j;
                bool ok = okk && ((n0 + r) < HH);
                rWv[0][j] = ok ? Wg[(n0 + r) * HH + gk] : 0.f;
                rWv[1][j] = ok ? Wm[(n0 + r) * HH + gk] : 0.f;
            }
        }
#pragma unroll
        for (int kk = 0; kk < BK; kk++) {
            float2 av = *reinterpret_cast<const float2*>(&sA[kk * LDA2 + m2]);
            u64 aa0 = pk2(av.x, av.x), aa1 = pk2(av.y, av.y);
#pragma unroll
            for (int p = 0; p < 2; p++) {
                ulonglong2 wv = *reinterpret_cast<const ulonglong2*>(
                                    &sW[(p * BK + kk) * LDW_ + n4]);
                fma2(acc[p][0][0], aa0, wv.x);
                fma2(acc[p][0][1], aa0, wv.y);
                fma2(acc[p][1][0], aa1, wv.x);
                fma2(acc[p][1][1], aa1, wv.y);
            }
        }
    }

    u64* scratch = reinterpret_cast<u64*>(smemblk);
    __syncthreads();
    if (g > 0) {
        int c = 0;
#pragma unroll
        for (int p = 0; p < 2; p++)
#pragma unroll
            for (int im = 0; im < 2; im++)
#pragma unroll
                for (int h = 0; h < 2; h++) {
                    scratch[((g - 1) * 8 + c) * 128 + l] = acc[p][im][h]; c++;
                }
    }
    __syncthreads();
    if (g == 0) {
#pragma unroll
        for (int gi = 0; gi < 3; gi++) {
            int c = 0;
#pragma unroll
            for (int p = 0; p < 2; p++)
#pragma unroll
                for (int im = 0; im < 2; im++)
#pragma unroll
                    for (int h = 0; h < 2; h++) {
                        add2(acc[p][im][h], scratch[(gi * 8 + c) * 128 + l]); c++;
                    }
        }
        float af[2][2][4];
#pragma unroll
        for (int p = 0; p < 2; p++)
#pragma unroll
            for (int im = 0; im < 2; im++) {
                up2(acc[p][im][0], af[p][im][0], af[p][im][1]);
                up2(acc[p][im][1], af[p][im][2], af[p][im][3]);
            }
#pragma unroll
        for (int jn = 0; jn < 4; jn++) {
            int n = n0 + n4 + jn;
            if (n >= HH) continue;
            float bgv = bg[n], bmv = bm[n];
            float base = 15.0f * sigf(bgv) * bmv;
#pragma unroll
            for (int im = 0; im < 2; im++) {
                int i = m0 + m2 + im;      // unguarded: pad rows harmless
                float u = af[0][im][jn] + bgv;
                float v = af[1][im][jn] + bmv;
                g_hinc[i * HH + n] = base + sigf(u) * v;
            }
        }
    }
}

// ===========================================================================
// k_gru_c: compacted GRU: gh = g_hinc @ Whh.T (3 parts), scatter to hv slot.
// ===========================================================================
__global__ __launch_bounds__(NT) void k_gru_c(int step,
        const float* __restrict__ ne,
        const float* __restrict__ Wih, const float* __restrict__ bih,
        const float* __restrict__ Whh, const float* __restrict__ bhh) {
    extern __shared__ __align__(16) float smemblk[];
    __shared__ int sidx[BM2];
    const int cnt = g_cnt[step];
    const int m0 = blockIdx.y * BM2;
    if (m0 >= cnt) return;
    const int n0 = blockIdx.x * BN;
    const int tid = threadIdx.x;
    const int g = tid >> 7, l = tid & 127;
    const int tx = l & 7, ty = l >> 3;
    const int n4 = tx * 4, m2 = ty * 2;
    const int kz = l & 31, r0 = l >> 5;
    const int kbase = g * KG;
    float* sA = smemblk + g * SA2_SZ;
    float* sW = smemblk + NGRP * SA2_SZ + g * SW3_SZ;
    const float* Hsrc = g_hinc;

    if (tid < BM2) sidx[tid] = g_idx[step * BB + m0 + tid];
    __syncthreads();

    u64 acc[3][2][2];
#pragma unroll
    for (int p = 0; p < 3; p++)
#pragma unroll
        for (int i = 0; i < 2; i++) { acc[p][i][0] = 0ull; acc[p][i][1] = 0ull; }

    float rAv[8], rWv[3][8];
    {
        int gk = kbase + kz;
#pragma unroll
        for (int i = 0; i < 8; i++)
            rAv[i] = Hsrc[(m0 + r0 + 4 * i) * HH + gk];
#pragma unroll
        for (int j = 0; j < 8; j++) {
            int r = r0 + 4 * j;
            bool ok = (n0 + r) < HH;
#pragma unroll
            for (int p = 0; p < 3; p++)
                rWv[p][j] = ok ? Whh[(p * HH + n0 + r) * HH + gk] : 0.f;
        }
    }

    for (int t = 0; t < NTG; t++) {
        GBAR(g);
#pragma unroll
        for (int i = 0; i < 8; i++) sA[kz * LDA2 + r0 + 4 * i] = rAv[i];
#pragma unroll
        for (int j = 0; j < 8; j++)
#pragma unroll
            for (int p = 0; p < 3; p++)
                sW[(p * BK + kz) * LDW_ + r0 + 4 * j] = rWv[p][j];
        GBAR(g);
        if (t + 1 < NTG) {
            int gk = kbase + (t + 1) * BK + kz;
            bool okk = gk < HH;
#pragma unroll
            for (int i = 0; i < 8; i++)
                rAv[i] = okk ? Hsrc[(m0 + r0 + 4 * i) * HH + gk] : 0.f;
#pragma unroll
            for (int j = 0; j < 8; j++) {
                int r = r0 + 4 * j;
                bool ok = okk && ((n0 + r) < HH);
#pragma unroll
                for (int p = 0; p < 3; p++)
                    rWv[p][j] = ok ? Whh[(p * HH + n0 + r) * HH + gk] : 0.f;
            }
        }
#pragma unroll
        for (int kk = 0; kk < BK; kk++) {
            float2 av = *reinterpret_cast<const float2*>(&sA[kk * LDA2 + m2]);
            u64 aa0 = pk2(av.x, av.x), aa1 = pk2(av.y, av.y);
#pragma unroll
            for (int p = 0; p < 3; p++) {
                ulonglong2 wv = *reinterpret_cast<const ulonglong2*>(
                                    &sW[(p * BK + kk) * LDW_ + n4]);
                fma2(acc[p][0][0], aa0, wv.x);
                fma2(acc[p][0][1], aa0, wv.y);
                fma2(acc[p][1][0], aa1, wv.x);
                fma2(acc[p][1][1], aa1, wv.y);
            }
        }
    }

    u64* scratch = reinterpret_cast<u64*>(smemblk);
    __syncthreads();
    if (g > 0) {
        int c = 0;
#pragma unroll
        for (int p = 0; p < 3; p++)
#pragma unroll
            for (int im = 0; im < 2; im++)
#pragma unroll
                for (int h = 0; h < 2; h++) {
                    scratch[((g - 1) * 12 + c) * 128 + l] = acc[p][im][h]; c++;
                }
    }
    __syncthreads();
    if (g == 0) {
#pragma unroll
        for (int gi = 0; gi < 3; gi++) {
            int c = 0;
#pragma unroll
            for (int p = 0; p < 3; p++)
#pragma unroll
                for (int im = 0; im < 2; im++)
#pragma unroll
                    for (int h = 0; h < 2; h++) {
                        add2(acc[p][im][h], scratch[(gi * 12 + c) * 128 + l]); c++;
                    }
        }
        float af[3][2][4];
#pragma unroll
        for (int p = 0; p < 3; p++)
#pragma unroll
            for (int im = 0; im < 2; im++) {
                up2(acc[p][im][0], af[p][im][0], af[p][im][1]);
                up2(acc[p][im][1], af[p][im][2], af[p][im][3]);
            }
        float* O = g_hv + (step + 1) * BB * HH;
#pragma unroll
        for (int im = 0; im < 2; im++) {
            int i = m0 + m2 + im;
            if (i >= cnt) continue;
            int b = sidx[m2 + im];
            float x[CC];
#pragma unroll
            for (int c2 = 0; c2 < CC; c2++) x[c2] = ne[b * SSZ * CC + step * CC + c2];
#pragma unroll
            for (int jn = 0; jn < 4; jn++) {
                int n = n0 + n4 + jn;
                if (n >= HH) continue;
                float gir = bih[n], giz = bih[HH + n], gin = bih[2 * HH + n];
#pragma unroll
                for (int c2 = 0; c2 < CC; c2++) {
                    gir += x[c2] * Wih[n * CC + c2];
                    giz += x[c2] * Wih[(HH + n) * CC + c2];
                    gin += x[c2] * Wih[(2 * HH + n) * CC + c2];
                }
                float ghr = af[0][im][jn] + bhh[n];
                float ghz = af[1][im][jn] + bhh[HH + n];
                float ghn = af[2][im][jn] + bhh[2 * HH + n];
                float r  = sigf(gir + ghr);
                float zg = sigf(giz + ghz);
                float nv = tanhf(gin + r * ghn);
                float hp = Hsrc[i * HH + n];
                O[b * HH + n] = (1.f - zg) * nv + zg * hp;
            }
        }
    }
}

// ---------------------------------------------------------------------------
// Merged post: rows [0,NDOTS) -> edge-logit dots; rows [NDOTS, NDOTS+NENC) ->
// node-encoding softmax. Warp per row, exact grid.
// ---------------------------------------------------------------------------
__global__ __launch_bounds__(256) void k_post(const float* __restrict__ We,
                                              const float* __restrict__ Wv,
                                              const float* __restrict__ bv,
                                              float* __restrict__ out2) {
    int row = blockIdx.x * 8 + (threadIdx.x >> 5);
    int lane = threadIdx.x & 31;
    if (row < NDOTS) {
        const float* hv = g_hv + row * HH;
        float a1 = 0.f, a2 = 0.f;
        for (int h = lane; h < HH; h += 32) {
            float v = hv[h];
            a1 += v * We[h];
            a2 += v * We[HH + h];
        }
#pragma unroll
        for (int o = 16; o; o >>= 1) {
            a1 += __shfl_xor_sync(0xffffffffu, a1, o);
            a2 += __shfl_xor_sync(0xffffffffu, a2, o);
        }
        if (lane == 0) { g_d1[row] = a1; g_d2[row] = a2; }
    } else {
        int r2 = row - NDOTS;
        int b = r2 >> 4, idx = r2 & 15;
        const float* hv = g_hv + (idx * BB + b) * HH;   // slot idx = hv_{idx-1}
        float l[CC];
#pragma unroll
        for (int c = 0; c < CC; c++) l[c] = 0.f;
        for (int h = lane; h < HH; h += 32) {
            float v = hv[h];
#pragma unroll
            for (int c = 0; c < CC; c++) l[c] += v * Wv[c * HH + h];
        }
#pragma unroll
        for (int c = 0; c < CC; c++)
#pragma unroll
            for (int o = 16; o; o >>= 1) l[c] += __shfl_xor_sync(0xffffffffu, l[c], o);
        if (lane == 0) {
            float mx = -1e30f;
#pragma unroll
            for (int c = 0; c < CC; c++) { l[c] += bv[c]; mx = fmaxf(mx, l[c]); }
            float s = 0.f;
#pragma unroll
            for (int c = 0; c < CC; c++) { l[c] = expf(l[c] - mx); s += l[c]; }
            float inv = 1.f / s;
#pragma unroll
            for (int c = 0; c < CC; c++) out2[r2 * CC + c] = l[c] * inv;
        }
    }
}

// ---------------------------------------------------------------------------
// Post: generated dep graph (hard threshold sigmoid(x)>=0.5 <=> x>=0)
// ---------------------------------------------------------------------------
__global__ void k_edges(const float* __restrict__ be_p, float* __restrict__ out) {
    int gid = blockIdx.x * blockDim.x + threadIdx.x;
    int j = gid & 15, idx = (gid >> 4) & 15, b = gid >> 8;
    float val = 0.f;
    if (idx > 0 && j < idx) {
        float t;
        if (j == idx - 1) t = g_d1[idx * BB + b] + g_d2[idx * BB + b];
        else              t = g_d1[(idx + 1) * BB + b] + g_d2[(j + 1) * BB + b];
        t += be_p[0];
        val = (t >= 0.f) ? 1.f : 0.f;
    }
    out[gid] = val;
}

// ---------------------------------------------------------------------------
extern "C" void kernel_launch(void* const* d_in, const int* in_sizes, int n_in,
                              void* d_out, int out_size) {
    const float* z      = (const float*)d_in[0];
    const float* dep    = (const float*)d_in[1];
    const float* ne     = (const float*)d_in[2];
    const float* W_lin1 = (const float*)d_in[3];
    const float* b_lin1 = (const float*)d_in[4];
    const float* W_vert = (const float*)d_in[5];
    const float* b_vert = (const float*)d_in[6];
    const float* W_edge = (const float*)d_in[7];
    const float* b_edge = (const float*)d_in[8];
    const float* W_gate = (const float*)d_in[9];
    const float* b_gate = (const float*)d_in[10];
    const float* W_map  = (const float*)d_in[11];
    const float* b_map  = (const float*)d_in[12];
    const float* W_ih   = (const float*)d_in[13];
    const float* b_ih   = (const float*)d_in[14];
    const float* W_hh   = (const float*)d_in[15];
    const float* b_hh   = (const float*)d_in[16];
    float* out = (float*)d_out;

    static int attr_done = 0;
    static cudaStream_t s2 = nullptr;
    static cudaEvent_t e0 = nullptr, e2 = nullptr;
    if (!attr_done) {
        cudaFuncSetAttribute(k_gru_full, cudaFuncAttributeMaxDynamicSharedMemorySize, GRU_SMEM);
        cudaFuncSetAttribute(k_lin1,  cudaFuncAttributeMaxDynamicSharedMemorySize, LIN_SMEM);
        cudaFuncSetAttribute(k_gru_c, cudaFuncAttributeMaxDynamicSharedMemorySize, GRUC_SMEM);
        cudaFuncSetAttribute(k_agm_c, cudaFuncAttributeMaxDynamicSharedMemorySize, AGMC_SMEM);
        cudaStreamCreateWithFlags(&s2, cudaStreamNonBlocking);
        cudaEventCreateWithFlags(&e0, cudaEventDisableTiming);
        cudaEventCreateWithFlags(&e2, cudaEventDisableTiming);
        attr_done = 1;
    }

    dim3 ggF(16, BB / BM);      // full-M kernels: (16, 8)
    dim3 ggC(16, BB / BM2);     // compacted kernels: (16, 16), early-exit by cnt

    // Fork: prolog smalls on s2, concurrent with lin1 + gru_full on origin.
    cudaEventRecord(e0, 0);
    cudaStreamWaitEvent(s2, e0, 0);
    k_ghc<<<(3 * HH + 7) / 8, 256, 0, s2>>>(W_hh, b_gate, b_map);
    k_outc<<<1, 512, 0, s2>>>(W_ih, b_ih, b_hh, b_gate, b_map);
    k_compact_par<<<1, 480, 0, s2>>>(dep);
    k_fill<<<(SSZ - 1) * BB / 8, 256, 0, s2>>>(dep, ne);
    cudaEventRecord(e2, s2);

    k_lin1<<<ggF, NT, LIN_SMEM>>>(z, W_lin1, b_lin1);               // slot 0
    k_gru_full<<<ggF, NT, GRU_SMEM>>>(ne, W_ih, b_ih, W_hh, b_hh);  // hv_0

    // Join: step chain needs fill/compact results.
    cudaStreamWaitEvent(0, e2, 0);
    for (int step = 1; step < SSZ; step++) {
        k_agm_c<<<ggC, NT, AGMC_SMEM>>>(step, W_gate, b_gate, W_map, b_map);
        k_gru_c<<<ggC, NT, GRUC_SMEM>>>(step, ne, W_ih, b_ih, W_hh, b_hh);
    }
    k_post<<<(NDOTS + NENC) / 8, 256>>>(W_edge, W_vert, b_vert, out + BB * SSZ * SSZ);
    k_edges<<<BB * SSZ * SSZ / 256, 256>>>(b_edge, out);
}